// round 1
// baseline (speedup 1.0000x reference)
#include <cuda_runtime.h>
#include <math.h>

#define BATCH   8
#define LSEQ    4096
#define INDIM   256
#define DMODEL  512
#define OUTDIM  256
#define ML      (BATCH*LSEQ)      /* 32768 */
#define CHUNK   64
#define NCH     (LSEQ/CHUNK)      /* 64 */

// ---------------- device scratch (statics: no alloc in kernel_launch) -------
__device__ float2 g_u[(size_t)ML*DMODEL];      // 134 MB  complex u = inputs @ Bc^T
__device__ float2 g_x[(size_t)ML*DMODEL];      // 134 MB  scan result (used when d_out can't hold interleaved x)
__device__ float2 g_carry[(size_t)BATCH*NCH*DMODEL];
__device__ float2 g_A[DMODEL];
__device__ float2 g_Ac[DMODEL];                // A^CHUNK
__device__ float2 g_Bc[(size_t)DMODEL*INDIM];  // scaled complex B

__device__ __forceinline__ float2 cmul(float2 a, float2 b) {
    return make_float2(a.x*b.x - a.y*b.y, a.x*b.y + a.y*b.x);
}

// ---------------- prep ------------------------------------------------------
__global__ void prep_A_kernel(const float* __restrict__ nu_log,
                              const float* __restrict__ theta_log) {
    int d = blockIdx.x*blockDim.x + threadIdx.x;
    if (d >= DMODEL) return;
    float r  = expf(-expf(nu_log[d]));
    float th = expf(theta_log[d]);
    float2 A = make_float2(r*cosf(th), r*sinf(th));
    g_A[d] = A;
    float2 p = make_float2(1.f, 0.f);
    #pragma unroll 8
    for (int i = 0; i < CHUNK; i++) p = cmul(p, A);
    g_Ac[d] = p;
}

__global__ void prep_B_kernel(const float* __restrict__ B_re,
                              const float* __restrict__ B_im,
                              const float* __restrict__ gamma_log) {
    int i = blockIdx.x*blockDim.x + threadIdx.x;
    if (i >= DMODEL*INDIM) return;
    int d = i / INDIM;
    float s = expf(gamma_log[d]);   // reference stores gamma, then exponentiates
    g_Bc[i] = make_float2(B_re[i]*s, B_im[i]*s);
}

// ---------------- u = inputs @ Bc^T  (real A x complex W) -------------------
// tile: 128(M) x 64(N complex), BK=16, 256 threads, each 8x4 complex outputs
__global__ __launch_bounds__(256)
void gemm_u_kernel(const float* __restrict__ inp) {
    __shared__ float  As[16][128 + 4];
    __shared__ float2 Ws[16][64 + 2];

    const int t  = threadIdx.x;
    const int tx = t & 15, ty = t >> 4;
    const int mBase = blockIdx.x * 128;
    const int nBase = blockIdx.y * 64;

    float2 acc[8][4];
    #pragma unroll
    for (int i = 0; i < 8; i++)
        #pragma unroll
        for (int j = 0; j < 4; j++) acc[i][j] = make_float2(0.f, 0.f);

    for (int kk = 0; kk < INDIM; kk += 16) {
        // A tile: 128x16 floats = 512 float4
        #pragma unroll
        for (int i = 0; i < 2; i++) {
            int idx = t + i*256;
            int row = idx >> 2, c4 = idx & 3;
            float4 v = *(const float4*)(inp + (size_t)(mBase+row)*INDIM + kk + c4*4);
            As[c4*4+0][row] = v.x; As[c4*4+1][row] = v.y;
            As[c4*4+2][row] = v.z; As[c4*4+3][row] = v.w;
        }
        // W tile: 64x16 float2 = 512 float4
        #pragma unroll
        for (int i = 0; i < 2; i++) {
            int idx = t + i*256;
            int row = idx >> 3, c = idx & 7;
            const float4* src = (const float4*)(g_Bc + (size_t)(nBase+row)*INDIM + kk);
            float4 v = src[c];
            Ws[c*2+0][row] = make_float2(v.x, v.y);
            Ws[c*2+1][row] = make_float2(v.z, v.w);
        }
        __syncthreads();
        #pragma unroll
        for (int k = 0; k < 16; k++) {
            float  a[8]; float2 w[4];
            #pragma unroll
            for (int i = 0; i < 8; i++) a[i] = As[k][ty*8 + i];
            #pragma unroll
            for (int j = 0; j < 4; j++) w[j] = Ws[k][tx + j*16];
            #pragma unroll
            for (int i = 0; i < 8; i++)
                #pragma unroll
                for (int j = 0; j < 4; j++) {
                    acc[i][j].x = fmaf(a[i], w[j].x, acc[i][j].x);
                    acc[i][j].y = fmaf(a[i], w[j].y, acc[i][j].y);
                }
        }
        __syncthreads();
    }
    #pragma unroll
    for (int i = 0; i < 8; i++) {
        int m = mBase + ty*8 + i;
        #pragma unroll
        for (int j = 0; j < 4; j++)
            g_u[(size_t)m*DMODEL + nBase + tx + j*16] = acc[i][j];
    }
}

// ---------------- chunked parallel scan: x_l = A x_{l-1} + u_l --------------
__global__ __launch_bounds__(256)
void scan_pass1_kernel() {
    int tid = blockIdx.x*blockDim.x + threadIdx.x;   // b*NCH*DMODEL + ch*DMODEL + d
    int d  = tid & (DMODEL-1);
    int ch = (tid >> 9) & (NCH-1);
    int b  = tid >> 15;
    if (b >= BATCH) return;
    float2 A = g_A[d];
    float2 x = make_float2(0.f, 0.f);
    const float2* up = g_u + ((size_t)(b*LSEQ + ch*CHUNK))*DMODEL + d;
    #pragma unroll 4
    for (int s = 0; s < CHUNK; s++) {
        float2 u = up[(size_t)s*DMODEL];
        float nx = fmaf(A.x, x.x, fmaf(-A.y, x.y, u.x));
        float ny = fmaf(A.x, x.y, fmaf( A.y, x.x, u.y));
        x = make_float2(nx, ny);
    }
    g_carry[((size_t)b*NCH + ch)*DMODEL + d] = x;
}

__global__ __launch_bounds__(256)
void scan_pass2_kernel() {
    int tid = blockIdx.x*blockDim.x + threadIdx.x;   // b*DMODEL + d
    if (tid >= BATCH*DMODEL) return;
    int d = tid & (DMODEL-1), b = tid >> 9;
    float2 Ac = g_Ac[d];
    float2 prev = make_float2(0.f, 0.f);
    for (int j = 0; j < NCH; j++) {
        size_t idx = ((size_t)b*NCH + j)*DMODEL + d;
        float2 cur = g_carry[idx];
        g_carry[idx] = prev;                         // exclusive: state entering chunk j
        float nx = fmaf(Ac.x, prev.x, fmaf(-Ac.y, prev.y, cur.x));
        float ny = fmaf(Ac.x, prev.y, fmaf( Ac.y, prev.x, cur.y));
        prev = make_float2(nx, ny);
    }
}

__global__ __launch_bounds__(256)
void scan_pass3_kernel(float2* __restrict__ xext, int use_ext, float* __restrict__ xreal) {
    int tid = blockIdx.x*blockDim.x + threadIdx.x;
    int d  = tid & (DMODEL-1);
    int ch = (tid >> 9) & (NCH-1);
    int b  = tid >> 15;
    if (b >= BATCH) return;
    float2 A = g_A[d];
    float2 x = g_carry[((size_t)b*NCH + ch)*DMODEL + d];
    size_t base = ((size_t)(b*LSEQ + ch*CHUNK))*DMODEL + d;
    const float2* up = g_u + base;
    float2* xo = (use_ext ? xext : g_x) + base;
    #pragma unroll 4
    for (int s = 0; s < CHUNK; s++) {
        float2 u = up[(size_t)s*DMODEL];
        float nx = fmaf(A.x, x.x, fmaf(-A.y, x.y, u.x));
        float ny = fmaf(A.x, x.y, fmaf( A.y, x.x, u.y));
        x = make_float2(nx, ny);
        xo[(size_t)s*DMODEL] = x;
        if (xreal) xreal[base + (size_t)s*DMODEL] = x.x;
    }
}

// ---------------- y = Re(x @ C^T) + inputs @ D^T -----------------------------
__global__ __launch_bounds__(256)
void gemm_y_kernel(const float2* __restrict__ xext, int use_ext,
                   const float* __restrict__ inp,
                   const float* __restrict__ C_re, const float* __restrict__ C_im,
                   const float* __restrict__ Dw,
                   float* __restrict__ yout, int pair) {
    __shared__ float2 Xs[16][128 + 2];
    __shared__ float2 Cs[16][64 + 2];
    __shared__ float  As2[16][128 + 4];
    __shared__ float  Ds[16][64 + 2];

    const float2* xsrc = use_ext ? xext : g_x;
    const int t  = threadIdx.x;
    const int tx = t & 15, ty = t >> 4;
    const int mBase = blockIdx.x * 128;
    const int nBase = blockIdx.y * 64;

    float acc[8][4];
    #pragma unroll
    for (int i = 0; i < 8; i++)
        #pragma unroll
        for (int j = 0; j < 4; j++) acc[i][j] = 0.f;

    // phase 1: sum over d_model of (xr*Cr - xi*Ci)
    for (int kk = 0; kk < DMODEL; kk += 16) {
        #pragma unroll
        for (int i = 0; i < 4; i++) {            // 128x16 float2 = 1024 float4
            int idx = t + i*256;
            int row = idx >> 3, c = idx & 7;
            const float4* src = (const float4*)(xsrc + (size_t)(mBase+row)*DMODEL + kk);
            float4 v = src[c];
            Xs[c*2+0][row] = make_float2(v.x, v.y);
            Xs[c*2+1][row] = make_float2(v.z, v.w);
        }
        #pragma unroll
        for (int i = 0; i < 4; i++) {            // 64x16 complex C
            int idx = t + i*256;
            int row = idx >> 4, k = idx & 15;
            size_t g = (size_t)(nBase+row)*DMODEL + kk + k;
            Cs[k][row] = make_float2(C_re[g], C_im[g]);
        }
        __syncthreads();
        #pragma unroll
        for (int k = 0; k < 16; k++) {
            float2 xa[8]; float2 cw[4];
            #pragma unroll
            for (int i = 0; i < 8; i++) xa[i] = Xs[k][ty*8 + i];
            #pragma unroll
            for (int j = 0; j < 4; j++) cw[j] = Cs[k][tx + j*16];
            #pragma unroll
            for (int i = 0; i < 8; i++)
                #pragma unroll
                for (int j = 0; j < 4; j++)
                    acc[i][j] = fmaf(xa[i].x, cw[j].x, fmaf(-xa[i].y, cw[j].y, acc[i][j]));
        }
        __syncthreads();
    }

    // phase 2: skip = inputs @ D^T
    for (int kk = 0; kk < INDIM; kk += 16) {
        #pragma unroll
        for (int i = 0; i < 2; i++) {
            int idx = t + i*256;
            int row = idx >> 2, c4 = idx & 3;
            float4 v = *(const float4*)(inp + (size_t)(mBase+row)*INDIM + kk + c4*4);
            As2[c4*4+0][row] = v.x; As2[c4*4+1][row] = v.y;
            As2[c4*4+2][row] = v.z; As2[c4*4+3][row] = v.w;
        }
        #pragma unroll
        for (int i = 0; i < 4; i++) {
            int idx = t + i*256;
            int row = idx >> 4, k = idx & 15;
            Ds[k][row] = Dw[(size_t)(nBase+row)*INDIM + kk + k];
        }
        __syncthreads();
        #pragma unroll
        for (int k = 0; k < 16; k++) {
            float a[8]; float w[4];
            #pragma unroll
            for (int i = 0; i < 8; i++) a[i] = As2[k][ty*8 + i];
            #pragma unroll
            for (int j = 0; j < 4; j++) w[j] = Ds[k][tx + j*16];
            #pragma unroll
            for (int i = 0; i < 8; i++)
                #pragma unroll
                for (int j = 0; j < 4; j++)
                    acc[i][j] = fmaf(a[i], w[j], acc[i][j]);
        }
        __syncthreads();
    }

    #pragma unroll
    for (int i = 0; i < 8; i++) {
        int m = mBase + ty*8 + i;
        #pragma unroll
        for (int j = 0; j < 4; j++) {
            size_t idx = (size_t)m*OUTDIM + nBase + tx + j*16;
            if (pair) { yout[idx*2] = acc[i][j]; yout[idx*2+1] = 0.f; }
            else      { yout[idx]   = acc[i][j]; }
        }
    }
}

// ---------------- host -------------------------------------------------------
extern "C" void kernel_launch(void* const* d_in, const int* in_sizes, int n_in,
                              void* d_out, int out_size) {
    const float* inputs    = (const float*)d_in[0];
    const float* nu_log    = (const float*)d_in[1];
    const float* theta_log = (const float*)d_in[2];
    const float* gamma_log = (const float*)d_in[3];
    const float* B_re      = (const float*)d_in[4];
    const float* B_im      = (const float*)d_in[5];
    const float* C_re      = (const float*)d_in[6];
    const float* C_im      = (const float*)d_in[7];
    const float* Dw        = (const float*)d_in[8];
    float* outF = (float*)d_out;

    const long long X = (long long)ML*DMODEL;   // 16,777,216 complex x elements
    const long long Y = (long long)ML*OUTDIM;   //  8,388,608 y elements
    // Output layout dispatch for the tuple (x complex64, y float32):
    //  2X+Y  floats : [x interleaved re/im][y]
    //  2X+2Y floats : [x interleaved][y as (re,0) pairs]   (promoted-complex view)
    //  X+Y   floats : [x.real][y]
    //  Y / 2X      : y-only / x-only fallbacks
    float2* xext = 0; int use_ext = 0; float* xreal = 0;
    float* yout = 0; int pair = 0;
    long long os = (long long)out_size;
    if      (os == 2*X + Y)   { xext = (float2*)d_out; use_ext = 1; yout = outF + 2*X; }
    else if (os == 2*X + 2*Y) { xext = (float2*)d_out; use_ext = 1; yout = outF + 2*X; pair = 1; }
    else if (os == X + Y)     { xreal = outF; yout = outF + X; }
    else if (os == Y)         { yout = outF; }
    else if (os == 2*X)       { xext = (float2*)d_out; use_ext = 1; }
    else                      { xext = (float2*)d_out; use_ext = 1; yout = outF + 2*X; pair = 1; }

    prep_A_kernel<<<2, 256>>>(nu_log, theta_log);
    prep_B_kernel<<<(DMODEL*INDIM)/256, 256>>>(B_re, B_im, gamma_log);

    dim3 gu(ML/128, DMODEL/64);
    gemm_u_kernel<<<gu, 256>>>(inputs);

    scan_pass1_kernel<<<(BATCH*NCH*DMODEL)/256, 256>>>();
    scan_pass2_kernel<<<(BATCH*DMODEL)/256, 256>>>();
    scan_pass3_kernel<<<(BATCH*NCH*DMODEL)/256, 256>>>(xext, use_ext, xreal);

    if (yout) {
        dim3 gy(ML/128, OUTDIM/64);
        gemm_y_kernel<<<gy, 256>>>(xext, use_ext, inputs, C_re, C_im, Dw, yout, pair);
    }
}

// round 4
// speedup vs baseline: 2.0689x; 2.0689x over previous
#include <cuda_runtime.h>
#include <cuda_bf16.h>
#include <stdint.h>
#include <math.h>

#define BATCH   8
#define LSEQ    4096
#define INDIM   256
#define DMODEL  512
#define OUTDIM  256
#define ML      (BATCH*LSEQ)      /* 32768 */
#define CHUNK   64
#define NCH     (LSEQ/CHUNK)      /* 64 */
#define K2      1280              /* xr(512) + xi(512) + inp(256) */
#define BK      32
#define PAD     40                /* padded smem row, bf16 elems (80 B) */
#define SBUF    (128*PAD*2)       /* bytes per smem buffer: 10240 */

// ---------------- device scratch -------------------------------------------
__device__ __align__(16) float2 g_u[(size_t)ML*DMODEL];      // 134 MB
__device__ __align__(16) float2 g_x[(size_t)ML*DMODEL];      // 134 MB fallback
__device__ __align__(16) float2 g_carry[(size_t)BATCH*NCH*DMODEL];
__device__ float2 g_A[DMODEL];
__device__ float2 g_Ac[DMODEL];
__device__ __align__(16) __nv_bfloat16 g_X2h[(size_t)ML*K2]; // 80 MB
__device__ __align__(16) __nv_bfloat16 g_X2l[(size_t)ML*K2]; // 80 MB
__device__ __align__(16) __nv_bfloat16 g_W1h[1024*256], g_W1l[1024*256];
__device__ __align__(16) __nv_bfloat16 g_W2h[256*K2],   g_W2l[256*K2];
__device__ __align__(16) float g_y[(size_t)ML*OUTDIM];       // 32 MB

__device__ __forceinline__ float2 cmul(float2 a, float2 b) {
    return make_float2(a.x*b.x - a.y*b.y, a.x*b.y + a.y*b.x);
}
__device__ __forceinline__ void split_bf16(float v, __nv_bfloat16& h, __nv_bfloat16& l) {
    h = __float2bfloat16_rn(v);
    l = __float2bfloat16_rn(v - __bfloat162float(h));
}

// ---------------- PTX helpers (all base-compute_103-legal) -------------------
__device__ __forceinline__ uint32_t smem_u32(const void* p) {
    uint32_t a;
    asm("{ .reg .u64 t; cvta.to.shared.u64 t, %1; cvt.u32.u64 %0, t; }" : "=r"(a) : "l"(p));
    return a;
}
__device__ __forceinline__ void cp16(uint32_t dst, const void* src) {
    asm volatile("cp.async.cg.shared.global [%0], [%1], 16;" :: "r"(dst), "l"(src));
}
#define CP_COMMIT()  asm volatile("cp.async.commit_group;")
#define CP_WAIT1()   asm volatile("cp.async.wait_group 1;")
#define CP_WAIT0()   asm volatile("cp.async.wait_group 0;")

#define LDSM4(r, addr) \
    asm volatile("ldmatrix.sync.aligned.m8n8.x4.shared.b16 {%0,%1,%2,%3}, [%4];" \
        : "=r"((r)[0]),"=r"((r)[1]),"=r"((r)[2]),"=r"((r)[3]) : "r"(addr))

__device__ __forceinline__ void mma16816(float* c, const uint32_t* a, const uint32_t* b) {
    asm volatile("mma.sync.aligned.m16n8k16.row.col.f32.bf16.bf16.f32 "
        "{%0,%1,%2,%3}, {%4,%5,%6,%7}, {%8,%9}, {%0,%1,%2,%3};"
        : "+f"(c[0]), "+f"(c[1]), "+f"(c[2]), "+f"(c[3])
        : "r"(a[0]),"r"(a[1]),"r"(a[2]),"r"(a[3]), "r"(b[0]),"r"(b[1]));
}

// ---------------- prep ------------------------------------------------------
__global__ void prep_A_kernel(const float* __restrict__ nu_log,
                              const float* __restrict__ theta_log) {
    int d = blockIdx.x*blockDim.x + threadIdx.x;
    if (d >= DMODEL) return;
    float r  = expf(-expf(nu_log[d]));
    float th = expf(theta_log[d]);
    float2 A = make_float2(r*cosf(th), r*sinf(th));
    g_A[d] = A;
    float2 p = make_float2(1.f, 0.f);
    #pragma unroll 8
    for (int i = 0; i < CHUNK; i++) p = cmul(p, A);
    g_Ac[d] = p;
}

__global__ void prep_W1_kernel(const float* __restrict__ B_re,
                               const float* __restrict__ B_im,
                               const float* __restrict__ gamma_log) {
    int i = blockIdx.x*blockDim.x + threadIdx.x;       // d*256 + h
    if (i >= DMODEL*INDIM) return;
    int d = i >> 8, h = i & 255;
    float s = expf(gamma_log[d]);
    __nv_bfloat16 hh, ll;
    split_bf16(B_re[i]*s, hh, ll);
    g_W1h[(size_t)(2*d)*256 + h] = hh; g_W1l[(size_t)(2*d)*256 + h] = ll;
    split_bf16(B_im[i]*s, hh, ll);
    g_W1h[(size_t)(2*d+1)*256 + h] = hh; g_W1l[(size_t)(2*d+1)*256 + h] = ll;
}

__global__ void prep_W2_kernel(const float* __restrict__ C_re,
                               const float* __restrict__ C_im,
                               const float* __restrict__ Dw) {
    int i = blockIdx.x*blockDim.x + threadIdx.x;       // n*K2 + k
    if (i >= OUTDIM*K2) return;
    int n = i / K2, k = i % K2;
    float v;
    if      (k < 512)  v =  C_re[(size_t)n*512 + k];
    else if (k < 1024) v = -C_im[(size_t)n*512 + (k-512)];
    else               v =  Dw  [(size_t)n*256 + (k-1024)];
    __nv_bfloat16 hh, ll; split_bf16(v, hh, ll);
    g_W2h[i] = hh; g_W2l[i] = ll;
}

__global__ void conv_inputs_kernel(const float* __restrict__ inp) {
    int i = blockIdx.x*blockDim.x + threadIdx.x;       // m*256 + h
    int m = i >> 8, h = i & 255;
    float v = inp[i];
    __nv_bfloat16 hh, ll; split_bf16(v, hh, ll);
    size_t o = (size_t)m*K2 + 1024 + h;
    g_X2h[o] = hh; g_X2l[o] = ll;
}

// ---------------- mma.sync GEMM: C = [Ah Ah Al] x [Bh Bl Bh]^T --------------
// CTA 128(M) x 128(N), 8 warps (warp tile 32x64), BK=32, double-buffered.
__device__ __forceinline__ void issue_loads(
    int t, uint32_t sA, uint32_t sB, int buf, int c, int nc,
    const __nv_bfloat16* Ah, const __nv_bfloat16* Al, long lda,
    const __nv_bfloat16* Bh, const __nv_bfloat16* Bl, long ldb,
    int mBase, int nBase)
{
    int cc = (c < nc) ? c : (c < 2*nc ? c - nc : c - 2*nc);
    const __nv_bfloat16* As = (c < 2*nc) ? Ah : Al;
    const __nv_bfloat16* Bs = (c < nc) ? Bh : (c < 2*nc ? Bl : Bh);
    long koff = (long)cc * BK;
    #pragma unroll
    for (int r = 0; r < 2; r++) {               // 128 rows x 4 x 16B each
        int ci = t + r*256; int row = ci >> 2, j = ci & 3;
        cp16(sA + buf*SBUF + row*(PAD*2) + j*16,
             As + (size_t)(mBase+row)*lda + koff + j*8);
        cp16(sB + buf*SBUF + row*(PAD*2) + j*16,
             Bs + (size_t)(nBase+row)*ldb + koff + j*8);
    }
    CP_COMMIT();
}

__global__ __launch_bounds__(256, 2)
void gemm_mma_kernel(int sel) {
    const __nv_bfloat16 *Ah, *Al, *Bh, *Bl;
    long lda, ldb, ldc; float* C; int K;
    if (sel == 0) {   // G1: u = inputs x W1^T  (N total = 1024)
        Ah = g_X2h + 1024; Al = g_X2l + 1024; lda = K2;
        Bh = g_W1h; Bl = g_W1l; ldb = 256;
        C = (float*)g_u; ldc = 1024; K = 256;
    } else {          // G2: y = X2 x W2^T     (N total = 256)
        Ah = g_X2h; Al = g_X2l; lda = K2;
        Bh = g_W2h; Bl = g_W2l; ldb = K2;
        C = g_y; ldc = 256; K = K2;
    }
    const int nc = K / BK, NC = 3*nc;
    const int t = threadIdx.x;
    const int wid = t >> 5, lane = t & 31;
    const int warp_m = wid & 3, warp_n = wid >> 2;
    const int mBase = blockIdx.y * 128;          // y = M rows (x-fastest shares A in L2)
    const int nBase = blockIdx.x * 128;

    __shared__ __align__(16) __nv_bfloat16 Asm[2][128*PAD];
    __shared__ __align__(16) __nv_bfloat16 Bsm[2][128*PAD];
    uint32_t sA = smem_u32(Asm), sB = smem_u32(Bsm);

    float acc[2][8][4];
    #pragma unroll
    for (int mi = 0; mi < 2; mi++)
        #pragma unroll
        for (int ni = 0; ni < 8; ni++)
            #pragma unroll
            for (int q = 0; q < 4; q++) acc[mi][ni][q] = 0.f;

    // ldmatrix per-thread byte offsets within a buffer
    uint32_t a_off[2], b_off[4];
    #pragma unroll
    for (int mi = 0; mi < 2; mi++) {
        int row = warp_m*32 + mi*16 + (lane & 15);
        int col = (lane >> 4) << 3;
        a_off[mi] = (uint32_t)((row*PAD + col) * 2);
    }
    #pragma unroll
    for (int p = 0; p < 4; p++) {
        int nrow = warp_n*64 + p*16 + (lane & 7) + ((lane >> 4) << 3);
        int col  = ((lane >> 3) & 1) << 3;
        b_off[p] = (uint32_t)((nrow*PAD + col) * 2);
    }

    issue_loads(t, sA, sB, 0, 0, nc, Ah, Al, lda, Bh, Bl, ldb, mBase, nBase);
    issue_loads(t, sA, sB, 1, 1, nc, Ah, Al, lda, Bh, Bl, ldb, mBase, nBase);

    for (int c = 0; c < NC; c++) {
        int buf = c & 1;
        if (c + 1 < NC) CP_WAIT1(); else CP_WAIT0();
        __syncthreads();

        uint32_t baseA = sA + buf*SBUF, baseB = sB + buf*SBUF;
        #pragma unroll
        for (int ks = 0; ks < 2; ks++) {         // two k16 steps per BK=32
            uint32_t afr[2][4], bfr[4][4];
            #pragma unroll
            for (int mi = 0; mi < 2; mi++) LDSM4(afr[mi], baseA + a_off[mi] + ks*32);
            #pragma unroll
            for (int p = 0; p < 4; p++)    LDSM4(bfr[p],  baseB + b_off[p]  + ks*32);
            #pragma unroll
            for (int mi = 0; mi < 2; mi++)
                #pragma unroll
                for (int ni = 0; ni < 8; ni++)
                    mma16816(acc[mi][ni], afr[mi], &bfr[ni >> 1][(ni & 1) * 2]);
        }
        __syncthreads();
        if (c + 2 < NC)
            issue_loads(t, sA, sB, buf, c+2, nc, Ah, Al, lda, Bh, Bl, ldb, mBase, nBase);
    }

    // epilogue: direct STG from accumulators
    #pragma unroll
    for (int mi = 0; mi < 2; mi++) {
        int r0 = mBase + warp_m*32 + mi*16 + (lane >> 2);
        #pragma unroll
        for (int ni = 0; ni < 8; ni++) {
            int col = nBase + warp_n*64 + ni*8 + (lane & 3)*2;
            *(float2*)(C + (size_t)r0*ldc + col)     = make_float2(acc[mi][ni][0], acc[mi][ni][1]);
            *(float2*)(C + (size_t)(r0+8)*ldc + col) = make_float2(acc[mi][ni][2], acc[mi][ni][3]);
        }
    }
}

// ---------------- chunked parallel scan --------------------------------------
__global__ __launch_bounds__(256)
void scan_pass1_kernel() {
    int tid = blockIdx.x*blockDim.x + threadIdx.x;
    int d  = tid & (DMODEL-1);
    int ch = (tid >> 9) & (NCH-1);
    int b  = tid >> 15;
    if (b >= BATCH) return;
    float2 A = g_A[d];
    float2 x = make_float2(0.f, 0.f);
    const float2* up = g_u + ((size_t)(b*LSEQ + ch*CHUNK))*DMODEL + d;
    #pragma unroll 4
    for (int s = 0; s < CHUNK; s++) {
        float2 u = up[(size_t)s*DMODEL];
        float nx = fmaf(A.x, x.x, fmaf(-A.y, x.y, u.x));
        float ny = fmaf(A.x, x.y, fmaf( A.y, x.x, u.y));
        x = make_float2(nx, ny);
    }
    g_carry[((size_t)b*NCH + ch)*DMODEL + d] = x;
}

__global__ __launch_bounds__(256)
void scan_pass2_kernel() {
    int tid = blockIdx.x*blockDim.x + threadIdx.x;
    if (tid >= BATCH*DMODEL) return;
    int d = tid & (DMODEL-1), b = tid >> 9;
    float2 Ac = g_Ac[d];
    float2 prev = make_float2(0.f, 0.f);
    for (int j = 0; j < NCH; j++) {
        size_t idx = ((size_t)b*NCH + j)*DMODEL + d;
        float2 cur = g_carry[idx];
        g_carry[idx] = prev;
        float nx = fmaf(Ac.x, prev.x, fmaf(-Ac.y, prev.y, cur.x));
        float ny = fmaf(Ac.x, prev.y, fmaf( Ac.y, prev.x, cur.y));
        prev = make_float2(nx, ny);
    }
}

__global__ __launch_bounds__(256)
void scan_pass3_kernel(float2* __restrict__ xext, int use_ext, float* __restrict__ xreal) {
    int tid = blockIdx.x*blockDim.x + threadIdx.x;
    int d  = tid & (DMODEL-1);
    int ch = (tid >> 9) & (NCH-1);
    int b  = tid >> 15;
    if (b >= BATCH) return;
    float2 A = g_A[d];
    float2 x = g_carry[((size_t)b*NCH + ch)*DMODEL + d];
    int m0 = b*LSEQ + ch*CHUNK;
    size_t base = (size_t)m0*DMODEL + d;
    const float2* up = g_u + base;
    float2* xo = (use_ext ? xext : g_x) + base;
    #pragma unroll 4
    for (int s = 0; s < CHUNK; s++) {
        float2 u = up[(size_t)s*DMODEL];
        float nx = fmaf(A.x, x.x, fmaf(-A.y, x.y, u.x));
        float ny = fmaf(A.x, x.y, fmaf( A.y, x.x, u.y));
        x = make_float2(nx, ny);
        xo[(size_t)s*DMODEL] = x;
        if (xreal) xreal[base + (size_t)s*DMODEL] = x.x;
        size_t xrow = (size_t)(m0 + s)*K2;
        __nv_bfloat16 hh, ll;
        split_bf16(x.x, hh, ll);
        g_X2h[xrow + d] = hh;       g_X2l[xrow + d] = ll;
        split_bf16(x.y, hh, ll);
        g_X2h[xrow + 512 + d] = hh; g_X2l[xrow + 512 + d] = ll;
    }
}

// ---------------- y format ---------------------------------------------------
__global__ __launch_bounds__(256)
void format_y_kernel(float* __restrict__ yout, int pair) {
    size_t i = (size_t)blockIdx.x*blockDim.x + threadIdx.x;
    if (i >= (size_t)ML*OUTDIM) return;
    float v = g_y[i];
    if (pair) { yout[2*i] = v; yout[2*i+1] = 0.f; }
    else      { yout[i]   = v; }
}

// ---------------- host -------------------------------------------------------
extern "C" void kernel_launch(void* const* d_in, const int* in_sizes, int n_in,
                              void* d_out, int out_size) {
    const float* inputs    = (const float*)d_in[0];
    const float* nu_log    = (const float*)d_in[1];
    const float* theta_log = (const float*)d_in[2];
    const float* gamma_log = (const float*)d_in[3];
    const float* B_re      = (const float*)d_in[4];
    const float* B_im      = (const float*)d_in[5];
    const float* C_re      = (const float*)d_in[6];
    const float* C_im      = (const float*)d_in[7];
    const float* Dw        = (const float*)d_in[8];
    float* outF = (float*)d_out;

    const long long X = (long long)ML*DMODEL;
    const long long Y = (long long)ML*OUTDIM;
    float2* xext = 0; int use_ext = 0; float* xreal = 0;
    float* yout = 0; int pair = 0;
    long long os = (long long)out_size;
    if      (os == 2*X + Y)   { xext = (float2*)d_out; use_ext = 1; yout = outF + 2*X; }
    else if (os == 2*X + 2*Y) { xext = (float2*)d_out; use_ext = 1; yout = outF + 2*X; pair = 1; }
    else if (os == X + Y)     { xreal = outF; yout = outF + X; }
    else if (os == Y)         { yout = outF; }
    else if (os == 2*X)       { xext = (float2*)d_out; use_ext = 1; }
    else                      { xext = (float2*)d_out; use_ext = 1; yout = outF + 2*X; pair = 1; }

    prep_A_kernel<<<2, 256>>>(nu_log, theta_log);
    prep_W1_kernel<<<(DMODEL*INDIM)/256, 256>>>(B_re, B_im, gamma_log);
    prep_W2_kernel<<<(OUTDIM*K2)/256, 256>>>(C_re, C_im, Dw);
    conv_inputs_kernel<<<(ML*INDIM)/256, 256>>>(inputs);

    // G1: u = inputs x W1^T  (M=32768, N=1024, K=256 -> K'=768)
    gemm_mma_kernel<<<dim3(1024/128, ML/128), 256>>>(0);

    scan_pass1_kernel<<<(BATCH*NCH*DMODEL)/256, 256>>>();
    scan_pass2_kernel<<<(BATCH*DMODEL)/256, 256>>>();
    scan_pass3_kernel<<<(BATCH*NCH*DMODEL)/256, 256>>>(xext, use_ext, xreal);

    if (yout) {
        // G2: y = [xr|xi|inp] x [Cr|-Ci|D]^T  (M=32768, N=256, K=1280 -> K'=3840)
        gemm_mma_kernel<<<dim3(256/128, ML/128), 256>>>(1);
        format_y_kernel<<<(int)((ML*(long long)OUTDIM + 255)/256), 256>>>(yout, pair);
    }
}

// round 5
// speedup vs baseline: 2.1171x; 1.0233x over previous
#include <cuda_runtime.h>
#include <cuda_bf16.h>
#include <stdint.h>
#include <math.h>

#define BATCH   8
#define LSEQ    4096
#define INDIM   256
#define DMODEL  512
#define OUTDIM  256
#define ML      (BATCH*LSEQ)      /* 32768 */
#define CHUNK   64
#define NCH     (LSEQ/CHUNK)      /* 64 */
#define K2      1280              /* xr(512) + xi(512) + inp(256) */
#define BK      32
#define PAD     40                /* padded smem row, bf16 elems (80 B) */
#define STAGES  4
#define ABYTES  (128*PAD*2)       /* 10240 B per operand tile */
#define STG_BYTES (2*ABYTES)      /* 20480 B per stage */
#define GEMM_SMEM (STAGES*STG_BYTES) /* 81920 B */

// ---------------- device scratch -------------------------------------------
__device__ __align__(16) float2 g_u[(size_t)ML*DMODEL];      // 134 MB
__device__ __align__(16) float2 g_x[(size_t)ML*DMODEL];      // 134 MB fallback
__device__ __align__(16) float2 g_carry[(size_t)BATCH*NCH*DMODEL];
__device__ float2 g_A[DMODEL];
__device__ float2 g_Ac[DMODEL];
__device__ __align__(16) __nv_bfloat16 g_X2h[(size_t)ML*K2]; // 80 MB
__device__ __align__(16) __nv_bfloat16 g_X2l[(size_t)ML*K2]; // 80 MB
__device__ __align__(16) __nv_bfloat16 g_W1h[1024*256], g_W1l[1024*256];
__device__ __align__(16) __nv_bfloat16 g_W2h[256*K2],   g_W2l[256*K2];

__device__ __forceinline__ float2 cmul(float2 a, float2 b) {
    return make_float2(a.x*b.x - a.y*b.y, a.x*b.y + a.y*b.x);
}
__device__ __forceinline__ void split_bf16(float v, __nv_bfloat16& h, __nv_bfloat16& l) {
    h = __float2bfloat16_rn(v);
    l = __float2bfloat16_rn(v - __bfloat162float(h));
}

// ---------------- PTX helpers ------------------------------------------------
__device__ __forceinline__ uint32_t smem_u32(const void* p) {
    uint32_t a;
    asm("{ .reg .u64 t; cvta.to.shared.u64 t, %1; cvt.u32.u64 %0, t; }" : "=r"(a) : "l"(p));
    return a;
}
__device__ __forceinline__ void cp16(uint32_t dst, const void* src) {
    asm volatile("cp.async.cg.shared.global [%0], [%1], 16;" :: "r"(dst), "l"(src));
}
#define CP_COMMIT()  asm volatile("cp.async.commit_group;")
#define CP_WAIT2()   asm volatile("cp.async.wait_group 2;")
#define CP_WAIT0()   asm volatile("cp.async.wait_group 0;")

#define LDSM4(r, addr) \
    asm volatile("ldmatrix.sync.aligned.m8n8.x4.shared.b16 {%0,%1,%2,%3}, [%4];" \
        : "=r"((r)[0]),"=r"((r)[1]),"=r"((r)[2]),"=r"((r)[3]) : "r"(addr))

__device__ __forceinline__ void mma16816(float* c, const uint32_t* a, const uint32_t* b) {
    asm volatile("mma.sync.aligned.m16n8k16.row.col.f32.bf16.bf16.f32 "
        "{%0,%1,%2,%3}, {%4,%5,%6,%7}, {%8,%9}, {%0,%1,%2,%3};"
        : "+f"(c[0]), "+f"(c[1]), "+f"(c[2]), "+f"(c[3])
        : "r"(a[0]),"r"(a[1]),"r"(a[2]),"r"(a[3]), "r"(b[0]),"r"(b[1]));
}

// ---------------- prep ------------------------------------------------------
__global__ void prep_A_kernel(const float* __restrict__ nu_log,
                              const float* __restrict__ theta_log) {
    int d = blockIdx.x*blockDim.x + threadIdx.x;
    if (d >= DMODEL) return;
    float r  = expf(-expf(nu_log[d]));
    float th = expf(theta_log[d]);
    float2 A = make_float2(r*cosf(th), r*sinf(th));
    g_A[d] = A;
    float2 p = make_float2(1.f, 0.f);
    #pragma unroll 8
    for (int i = 0; i < CHUNK; i++) p = cmul(p, A);
    g_Ac[d] = p;
}

__global__ void prep_W1_kernel(const float* __restrict__ B_re,
                               const float* __restrict__ B_im,
                               const float* __restrict__ gamma_log) {
    int i = blockIdx.x*blockDim.x + threadIdx.x;       // d*256 + h
    if (i >= DMODEL*INDIM) return;
    int d = i >> 8, h = i & 255;
    float s = expf(gamma_log[d]);
    __nv_bfloat16 hh, ll;
    split_bf16(B_re[i]*s, hh, ll);
    g_W1h[(size_t)(2*d)*256 + h] = hh; g_W1l[(size_t)(2*d)*256 + h] = ll;
    split_bf16(B_im[i]*s, hh, ll);
    g_W1h[(size_t)(2*d+1)*256 + h] = hh; g_W1l[(size_t)(2*d+1)*256 + h] = ll;
}

__global__ void prep_W2_kernel(const float* __restrict__ C_re,
                               const float* __restrict__ C_im,
                               const float* __restrict__ Dw) {
    int i = blockIdx.x*blockDim.x + threadIdx.x;       // n*K2 + k
    if (i >= OUTDIM*K2) return;
    int n = i / K2, k = i % K2;
    float v;
    if      (k < 512)  v =  C_re[(size_t)n*512 + k];
    else if (k < 1024) v = -C_im[(size_t)n*512 + (k-512)];
    else               v =  Dw  [(size_t)n*256 + (k-1024)];
    __nv_bfloat16 hh, ll; split_bf16(v, hh, ll);
    g_W2h[i] = hh; g_W2l[i] = ll;
}

// vectorized: 8 floats in, 8 bf16 hi + 8 bf16 lo out (16B stores)
__global__ void conv_inputs_kernel(const float* __restrict__ inp) {
    int i = blockIdx.x*blockDim.x + threadIdx.x;       // ML*32 groups
    int m = i >> 5, h8 = (i & 31) << 3;
    const float4* src = (const float4*)(inp + (size_t)m*INDIM + h8);
    float4 v0 = src[0], v1 = src[1];
    float vals[8] = {v0.x, v0.y, v0.z, v0.w, v1.x, v1.y, v1.z, v1.w};
    __nv_bfloat16 hi[8], lo[8];
    #pragma unroll
    for (int j = 0; j < 8; j++) split_bf16(vals[j], hi[j], lo[j]);
    size_t o = (size_t)m*K2 + 1024 + h8;
    *(uint4*)(g_X2h + o) = *(uint4*)hi;
    *(uint4*)(g_X2l + o) = *(uint4*)lo;
}

// ---------------- mma.sync GEMM: C = [Ah Ah Al] x [Bh Bl Bh]^T --------------
// CTA 128(M) x 128(N), 8 warps (warp tile 32x64), BK=32, 4-stage cp.async ring.
__device__ __forceinline__ void issue_loads(
    int t, uint32_t sbase, int stg, int c, int nc,
    const __nv_bfloat16* Ah, const __nv_bfloat16* Al, long lda,
    const __nv_bfloat16* Bh, const __nv_bfloat16* Bl, long ldb,
    int mBase, int nBase)
{
    int cc = (c < nc) ? c : (c < 2*nc ? c - nc : c - 2*nc);
    const __nv_bfloat16* As = (c < 2*nc) ? Ah : Al;
    const __nv_bfloat16* Bs = (c < nc) ? Bh : (c < 2*nc ? Bl : Bh);
    long koff = (long)cc * BK;
    uint32_t aBuf = sbase + stg*STG_BYTES;
    uint32_t bBuf = aBuf + ABYTES;
    #pragma unroll
    for (int r = 0; r < 2; r++) {               // 128 rows x 4 x 16B each operand
        int ci = t + r*256; int row = ci >> 2, j = ci & 3;
        cp16(aBuf + row*(PAD*2) + j*16, As + (size_t)(mBase+row)*lda + koff + j*8);
        cp16(bBuf + row*(PAD*2) + j*16, Bs + (size_t)(nBase+row)*ldb + koff + j*8);
    }
    CP_COMMIT();
}

__global__ __launch_bounds__(256, 2)
void gemm_mma_kernel(int sel, float* __restrict__ yout, int pair) {
    const __nv_bfloat16 *Ah, *Al, *Bh, *Bl;
    long lda, ldb; int K;
    if (sel == 0) {   // G1: u = inputs x W1^T  (N total = 1024)
        Ah = g_X2h + 1024; Al = g_X2l + 1024; lda = K2;
        Bh = g_W1h; Bl = g_W1l; ldb = 256; K = 256;
    } else {          // G2: y = X2 x W2^T     (N total = 256)
        Ah = g_X2h; Al = g_X2l; lda = K2;
        Bh = g_W2h; Bl = g_W2l; ldb = K2; K = K2;
    }
    const int nc = K / BK, NC = 3*nc;
    const int t = threadIdx.x;
    const int wid = t >> 5, lane = t & 31;
    const int warp_m = wid & 3, warp_n = wid >> 2;
    const int mBase = blockIdx.y * 128;
    const int nBase = blockIdx.x * 128;

    extern __shared__ __align__(16) char smem[];
    uint32_t sbase = smem_u32(smem);

    float acc[2][8][4];
    #pragma unroll
    for (int mi = 0; mi < 2; mi++)
        #pragma unroll
        for (int ni = 0; ni < 8; ni++)
            #pragma unroll
            for (int q = 0; q < 4; q++) acc[mi][ni][q] = 0.f;

    uint32_t a_off[2], b_off[4];
    #pragma unroll
    for (int mi = 0; mi < 2; mi++) {
        int row = warp_m*32 + mi*16 + (lane & 15);
        int col = (lane >> 4) << 3;
        a_off[mi] = (uint32_t)((row*PAD + col) * 2);
    }
    #pragma unroll
    for (int p = 0; p < 4; p++) {
        int nrow = warp_n*64 + p*16 + (lane & 7) + ((lane >> 4) << 3);
        int col  = ((lane >> 3) & 1) << 3;
        b_off[p] = (uint32_t)((nrow*PAD + col) * 2);
    }

    // prologue: fill 3 of 4 stages
    issue_loads(t, sbase, 0, 0, nc, Ah, Al, lda, Bh, Bl, ldb, mBase, nBase);
    issue_loads(t, sbase, 1, 1, nc, Ah, Al, lda, Bh, Bl, ldb, mBase, nBase);
    issue_loads(t, sbase, 2, 2, nc, Ah, Al, lda, Bh, Bl, ldb, mBase, nBase);

    for (int c = 0; c < NC; c++) {
        int stg = c & 3;
        CP_WAIT2();                      // stage c ready (<=2 groups pending)
        __syncthreads();                 // all warps done with stage (c+3)&3 from iter c-1
        if (c + 3 < NC)
            issue_loads(t, sbase, (c+3) & 3, c+3, nc, Ah, Al, lda, Bh, Bl, ldb, mBase, nBase);
        else
            CP_COMMIT();                 // keep group count in lockstep

        uint32_t baseA = sbase + stg*STG_BYTES, baseB = baseA + ABYTES;
        #pragma unroll
        for (int ks = 0; ks < 2; ks++) {
            uint32_t afr[2][4], bfr[4][4];
            #pragma unroll
            for (int mi = 0; mi < 2; mi++) LDSM4(afr[mi], baseA + a_off[mi] + ks*32);
            #pragma unroll
            for (int p = 0; p < 4; p++)    LDSM4(bfr[p],  baseB + b_off[p]  + ks*32);
            #pragma unroll
            for (int mi = 0; mi < 2; mi++)
                #pragma unroll
                for (int ni = 0; ni < 8; ni++)
                    mma16816(acc[mi][ni], afr[mi], &bfr[ni >> 1][(ni & 1) * 2]);
        }
    }
    CP_WAIT0();

    if (sel == 0) {
        float* C = (float*)g_u;          // ldc = 1024
        #pragma unroll
        for (int mi = 0; mi < 2; mi++) {
            int r0 = mBase + warp_m*32 + mi*16 + (lane >> 2);
            #pragma unroll
            for (int ni = 0; ni < 8; ni++) {
                int col = nBase + warp_n*64 + ni*8 + (lane & 3)*2;
                *(float2*)(C + (size_t)r0*1024 + col)     = make_float2(acc[mi][ni][0], acc[mi][ni][1]);
                *(float2*)(C + (size_t)(r0+8)*1024 + col) = make_float2(acc[mi][ni][2], acc[mi][ni][3]);
            }
        }
    } else if (pair) {                   // y as (re,0) complex pairs
        #pragma unroll
        for (int mi = 0; mi < 2; mi++) {
            int r0 = mBase + warp_m*32 + mi*16 + (lane >> 2);
            #pragma unroll
            for (int ni = 0; ni < 8; ni++) {
                int col = nBase + warp_n*64 + ni*8 + (lane & 3)*2;
                *(float4*)(yout + 2*((size_t)r0*256 + col)) =
                    make_float4(acc[mi][ni][0], 0.f, acc[mi][ni][1], 0.f);
                *(float4*)(yout + 2*((size_t)(r0+8)*256 + col)) =
                    make_float4(acc[mi][ni][2], 0.f, acc[mi][ni][3], 0.f);
            }
        }
    } else {
        #pragma unroll
        for (int mi = 0; mi < 2; mi++) {
            int r0 = mBase + warp_m*32 + mi*16 + (lane >> 2);
            #pragma unroll
            for (int ni = 0; ni < 8; ni++) {
                int col = nBase + warp_n*64 + ni*8 + (lane & 3)*2;
                *(float2*)(yout + (size_t)r0*256 + col)     = make_float2(acc[mi][ni][0], acc[mi][ni][1]);
                *(float2*)(yout + (size_t)(r0+8)*256 + col) = make_float2(acc[mi][ni][2], acc[mi][ni][3]);
            }
        }
    }
}

// ---------------- chunked parallel scan --------------------------------------
__global__ __launch_bounds__(256)
void scan_pass1_kernel() {
    int tid = blockIdx.x*blockDim.x + threadIdx.x;
    int d  = tid & (DMODEL-1);
    int ch = (tid >> 9) & (NCH-1);
    int b  = tid >> 15;
    if (b >= BATCH) return;
    float2 A = g_A[d];
    float2 x = make_float2(0.f, 0.f);
    const float2* up = g_u + ((size_t)(b*LSEQ + ch*CHUNK))*DMODEL + d;
    #pragma unroll 4
    for (int s = 0; s < CHUNK; s++) {
        float2 u = up[(size_t)s*DMODEL];
        float nx = fmaf(A.x, x.x, fmaf(-A.y, x.y, u.x));
        float ny = fmaf(A.x, x.y, fmaf( A.y, x.x, u.y));
        x = make_float2(nx, ny);
    }
    g_carry[((size_t)b*NCH + ch)*DMODEL + d] = x;
}

__global__ __launch_bounds__(256)
void scan_pass2_kernel() {
    int tid = blockIdx.x*blockDim.x + threadIdx.x;
    if (tid >= BATCH*DMODEL) return;
    int d = tid & (DMODEL-1), b = tid >> 9;
    float2 Ac = g_Ac[d];
    float2 prev = make_float2(0.f, 0.f);
    for (int j = 0; j < NCH; j++) {
        size_t idx = ((size_t)b*NCH + j)*DMODEL + d;
        float2 cur = g_carry[idx];
        g_carry[idx] = prev;
        float nx = fmaf(Ac.x, prev.x, fmaf(-Ac.y, prev.y, cur.x));
        float ny = fmaf(Ac.x, prev.y, fmaf( Ac.y, prev.x, cur.y));
        prev = make_float2(nx, ny);
    }
}

__global__ __launch_bounds__(256)
void scan_pass3_kernel(float2* __restrict__ xext, int use_ext, float* __restrict__ xreal) {
    int tid = blockIdx.x*blockDim.x + threadIdx.x;
    int d  = tid & (DMODEL-1);
    int ch = (tid >> 9) & (NCH-1);
    int b  = tid >> 15;
    if (b >= BATCH) return;
    float2 A = g_A[d];
    float2 x = g_carry[((size_t)b*NCH + ch)*DMODEL + d];
    int m0 = b*LSEQ + ch*CHUNK;
    size_t base = (size_t)m0*DMODEL + d;
    const float2* up = g_u + base;
    float2* xo = (use_ext ? xext : g_x) + base;
    #pragma unroll 4
    for (int s = 0; s < CHUNK; s++) {
        float2 u = up[(size_t)s*DMODEL];
        float nx = fmaf(A.x, x.x, fmaf(-A.y, x.y, u.x));
        float ny = fmaf(A.x, x.y, fmaf( A.y, x.x, u.y));
        x = make_float2(nx, ny);
        xo[(size_t)s*DMODEL] = x;
        if (xreal) xreal[base + (size_t)s*DMODEL] = x.x;
        size_t xrow = (size_t)(m0 + s)*K2;
        __nv_bfloat16 hh, ll;
        split_bf16(x.x, hh, ll);
        g_X2h[xrow + d] = hh;       g_X2l[xrow + d] = ll;
        split_bf16(x.y, hh, ll);
        g_X2h[xrow + 512 + d] = hh; g_X2l[xrow + 512 + d] = ll;
    }
}

// ---------------- host -------------------------------------------------------
extern "C" void kernel_launch(void* const* d_in, const int* in_sizes, int n_in,
                              void* d_out, int out_size) {
    const float* inputs    = (const float*)d_in[0];
    const float* nu_log    = (const float*)d_in[1];
    const float* theta_log = (const float*)d_in[2];
    const float* gamma_log = (const float*)d_in[3];
    const float* B_re      = (const float*)d_in[4];
    const float* B_im      = (const float*)d_in[5];
    const float* C_re      = (const float*)d_in[6];
    const float* C_im      = (const float*)d_in[7];
    const float* Dw        = (const float*)d_in[8];
    float* outF = (float*)d_out;

    const long long X = (long long)ML*DMODEL;
    const long long Y = (long long)ML*OUTDIM;
    float2* xext = 0; int use_ext = 0; float* xreal = 0;
    float* yout = 0; int pair = 0;
    long long os = (long long)out_size;
    if      (os == 2*X + Y)   { xext = (float2*)d_out; use_ext = 1; yout = outF + 2*X; }
    else if (os == 2*X + 2*Y) { xext = (float2*)d_out; use_ext = 1; yout = outF + 2*X; pair = 1; }
    else if (os == X + Y)     { xreal = outF; yout = outF + X; }
    else if (os == Y)         { yout = outF; }
    else if (os == 2*X)       { xext = (float2*)d_out; use_ext = 1; }
    else                      { xext = (float2*)d_out; use_ext = 1; yout = outF + 2*X; pair = 1; }

    cudaFuncSetAttribute(gemm_mma_kernel,
                         cudaFuncAttributeMaxDynamicSharedMemorySize, GEMM_SMEM);

    prep_A_kernel<<<2, 256>>>(nu_log, theta_log);
    prep_W1_kernel<<<(DMODEL*INDIM)/256, 256>>>(B_re, B_im, gamma_log);
    prep_W2_kernel<<<(OUTDIM*K2)/256, 256>>>(C_re, C_im, Dw);
    conv_inputs_kernel<<<(ML*32)/256, 256>>>(inputs);

    // G1: u = inputs x W1^T  (M=32768, N=1024, K=256 -> K'=768)
    gemm_mma_kernel<<<dim3(1024/128, ML/128), 256, GEMM_SMEM>>>(0, 0, 0);

    scan_pass1_kernel<<<(BATCH*NCH*DMODEL)/256, 256>>>();
    scan_pass2_kernel<<<(BATCH*DMODEL)/256, 256>>>();
    scan_pass3_kernel<<<(BATCH*NCH*DMODEL)/256, 256>>>(xext, use_ext, xreal);

    if (yout) {
        // G2: y = [xr|xi|inp] x [Cr|-Ci|D]^T  (M=32768, N=256, K=1280 -> K'=3840)
        gemm_mma_kernel<<<dim3(256/128, ML/128), 256, GEMM_SMEM>>>(1, yout, pair);
    }
}

// round 6
// speedup vs baseline: 2.8513x; 1.3468x over previous
#include <cuda_runtime.h>
#include <cuda_fp16.h>
#include <stdint.h>
#include <math.h>

#define BATCH   8
#define LSEQ    4096
#define INDIM   256
#define DMODEL  512
#define OUTDIM  256
#define ML      (BATCH*LSEQ)      /* 32768 */
#define CHUNK   64
#define NCH     (LSEQ/CHUNK)      /* 64 */
#define K2      1280              /* xr(512) + xi(512) + inp(256) */
#define BK      32
#define PAD     40                /* padded smem row, fp16 elems (80 B) */
#define STAGES  4
#define ABYTES  (128*PAD*2)       /* 10240 B per operand tile */
#define STG_BYTES (2*ABYTES)      /* 20480 B per stage */
#define GEMM_SMEM (STAGES*STG_BYTES) /* 81920 B */

// ---------------- device scratch -------------------------------------------
__device__ __align__(16) float2 g_u[(size_t)ML*DMODEL];      // 134 MB
__device__ __align__(16) float2 g_x[(size_t)ML*DMODEL];      // 134 MB fallback
__device__ __align__(16) float2 g_carry[(size_t)BATCH*NCH*DMODEL];
__device__ float2 g_A[DMODEL];
__device__ float2 g_Ac[DMODEL];
__device__ __align__(16) __half g_X2h[(size_t)ML*K2];        // 80 MB (activation hi)
__device__ __align__(16) __half g_X2l[(size_t)ML*K2];        // 80 MB (activation lo)
__device__ __align__(16) __half g_W1[1024*256];              // weights, fp16 (hi only)
__device__ __align__(16) __half g_W2[256*K2];

__device__ __forceinline__ float2 cmul(float2 a, float2 b) {
    return make_float2(a.x*b.x - a.y*b.y, a.x*b.y + a.y*b.x);
}
__device__ __forceinline__ void split_f16(float v, __half& h, __half& l) {
    h = __float2half_rn(v);
    l = __float2half_rn(v - __half2float(h));
}

// ---------------- PTX helpers ------------------------------------------------
__device__ __forceinline__ uint32_t smem_u32(const void* p) {
    uint32_t a;
    asm("{ .reg .u64 t; cvta.to.shared.u64 t, %1; cvt.u32.u64 %0, t; }" : "=r"(a) : "l"(p));
    return a;
}
__device__ __forceinline__ void cp16(uint32_t dst, const void* src) {
    asm volatile("cp.async.cg.shared.global [%0], [%1], 16;" :: "r"(dst), "l"(src));
}
#define CP_COMMIT()  asm volatile("cp.async.commit_group;")
#define CP_WAIT2()   asm volatile("cp.async.wait_group 2;")
#define CP_WAIT0()   asm volatile("cp.async.wait_group 0;")

#define LDSM4(r, addr) \
    asm volatile("ldmatrix.sync.aligned.m8n8.x4.shared.b16 {%0,%1,%2,%3}, [%4];" \
        : "=r"((r)[0]),"=r"((r)[1]),"=r"((r)[2]),"=r"((r)[3]) : "r"(addr))

__device__ __forceinline__ void mma16816(float* c, const uint32_t* a, const uint32_t* b) {
    asm volatile("mma.sync.aligned.m16n8k16.row.col.f32.f16.f16.f32 "
        "{%0,%1,%2,%3}, {%4,%5,%6,%7}, {%8,%9}, {%0,%1,%2,%3};"
        : "+f"(c[0]), "+f"(c[1]), "+f"(c[2]), "+f"(c[3])
        : "r"(a[0]),"r"(a[1]),"r"(a[2]),"r"(a[3]), "r"(b[0]),"r"(b[1]));
}

// ---------------- prep ------------------------------------------------------
__global__ void prep_A_kernel(const float* __restrict__ nu_log,
                              const float* __restrict__ theta_log) {
    int d = blockIdx.x*blockDim.x + threadIdx.x;
    if (d >= DMODEL) return;
    float r  = expf(-expf(nu_log[d]));
    float th = expf(theta_log[d]);
    float2 A = make_float2(r*cosf(th), r*sinf(th));
    g_A[d] = A;
    float2 p = make_float2(1.f, 0.f);
    #pragma unroll 8
    for (int i = 0; i < CHUNK; i++) p = cmul(p, A);
    g_Ac[d] = p;
}

__global__ void prep_W1_kernel(const float* __restrict__ B_re,
                               const float* __restrict__ B_im,
                               const float* __restrict__ gamma_log) {
    int i = blockIdx.x*blockDim.x + threadIdx.x;       // d*256 + h
    if (i >= DMODEL*INDIM) return;
    int d = i >> 8, h = i & 255;
    float s = expf(gamma_log[d]);
    g_W1[(size_t)(2*d)*256   + h] = __float2half_rn(B_re[i]*s);
    g_W1[(size_t)(2*d+1)*256 + h] = __float2half_rn(B_im[i]*s);
}

__global__ void prep_W2_kernel(const float* __restrict__ C_re,
                               const float* __restrict__ C_im,
                               const float* __restrict__ Dw) {
    int i = blockIdx.x*blockDim.x + threadIdx.x;       // n*K2 + k
    if (i >= OUTDIM*K2) return;
    int n = i / K2, k = i % K2;
    float v;
    if      (k < 512)  v =  C_re[(size_t)n*512 + k];
    else if (k < 1024) v = -C_im[(size_t)n*512 + (k-512)];
    else               v =  Dw  [(size_t)n*256 + (k-1024)];
    g_W2[i] = __float2half_rn(v);
}

// vectorized: 8 floats in, 8 fp16 hi + 8 fp16 lo out (16B stores)
__global__ void conv_inputs_kernel(const float* __restrict__ inp) {
    int i = blockIdx.x*blockDim.x + threadIdx.x;       // ML*32 groups
    int m = i >> 5, h8 = (i & 31) << 3;
    const float4* src = (const float4*)(inp + (size_t)m*INDIM + h8);
    float4 v0 = src[0], v1 = src[1];
    float vals[8] = {v0.x, v0.y, v0.z, v0.w, v1.x, v1.y, v1.z, v1.w};
    __half hi[8], lo[8];
    #pragma unroll
    for (int j = 0; j < 8; j++) split_f16(vals[j], hi[j], lo[j]);
    size_t o = (size_t)m*K2 + 1024 + h8;
    *(uint4*)(g_X2h + o) = *(uint4*)hi;
    *(uint4*)(g_X2l + o) = *(uint4*)lo;
}

// ---------------- mma.sync GEMM: C = [Ah Al] x [Bh Bh]^T --------------------
// CTA 128(M) x 128(N), 8 warps (warp tile 32x64), BK=32, 4-stage cp.async ring.
__device__ __forceinline__ void issue_loads(
    int t, uint32_t sbase, int stg, int c, int nc,
    const __half* Ah, const __half* Al, long lda,
    const __half* Bw, long ldb,
    int mBase, int nBase)
{
    int cc = (c < nc) ? c : c - nc;
    const __half* As = (c < nc) ? Ah : Al;
    long koff = (long)cc * BK;
    uint32_t aBuf = sbase + stg*STG_BYTES;
    uint32_t bBuf = aBuf + ABYTES;
    #pragma unroll
    for (int r = 0; r < 2; r++) {               // 128 rows x 4 x 16B each operand
        int ci = t + r*256; int row = ci >> 2, j = ci & 3;
        cp16(aBuf + row*(PAD*2) + j*16, As + (size_t)(mBase+row)*lda + koff + j*8);
        cp16(bBuf + row*(PAD*2) + j*16, Bw + (size_t)(nBase+row)*ldb + koff + j*8);
    }
    CP_COMMIT();
}

__global__ __launch_bounds__(256, 2)
void gemm_mma_kernel(int sel, float* __restrict__ yout, int pair) {
    const __half *Ah, *Al, *Bw;
    long lda, ldb; int K;
    if (sel == 0) {   // G1: u = inputs x W1^T  (N total = 1024)
        Ah = g_X2h + 1024; Al = g_X2l + 1024; lda = K2;
        Bw = g_W1; ldb = 256; K = 256;
    } else {          // G2: y = X2 x W2^T     (N total = 256)
        Ah = g_X2h; Al = g_X2l; lda = K2;
        Bw = g_W2; ldb = K2; K = K2;
    }
    const int nc = K / BK, NC = 2*nc;
    const int t = threadIdx.x;
    const int wid = t >> 5, lane = t & 31;
    const int warp_m = wid & 3, warp_n = wid >> 2;
    const int mBase = blockIdx.y * 128;
    const int nBase = blockIdx.x * 128;

    extern __shared__ __align__(16) char smem[];
    uint32_t sbase = smem_u32(smem);

    float acc[2][8][4];
    #pragma unroll
    for (int mi = 0; mi < 2; mi++)
        #pragma unroll
        for (int ni = 0; ni < 8; ni++)
            #pragma unroll
            for (int q = 0; q < 4; q++) acc[mi][ni][q] = 0.f;

    uint32_t a_off[2], b_off[4];
    #pragma unroll
    for (int mi = 0; mi < 2; mi++) {
        int row = warp_m*32 + mi*16 + (lane & 15);
        int col = (lane >> 4) << 3;
        a_off[mi] = (uint32_t)((row*PAD + col) * 2);
    }
    #pragma unroll
    for (int p = 0; p < 4; p++) {
        int nrow = warp_n*64 + p*16 + (lane & 7) + ((lane >> 4) << 3);
        int col  = ((lane >> 3) & 1) << 3;
        b_off[p] = (uint32_t)((nrow*PAD + col) * 2);
    }

    // prologue: fill 3 of 4 stages
    issue_loads(t, sbase, 0, 0, nc, Ah, Al, lda, Bw, ldb, mBase, nBase);
    issue_loads(t, sbase, 1, 1, nc, Ah, Al, lda, Bw, ldb, mBase, nBase);
    issue_loads(t, sbase, 2, 2, nc, Ah, Al, lda, Bw, ldb, mBase, nBase);

    for (int c = 0; c < NC; c++) {
        int stg = c & 3;
        CP_WAIT2();                      // stage c ready (<=2 groups pending)
        __syncthreads();                 // all warps done with stage (c+3)&3
        if (c + 3 < NC)
            issue_loads(t, sbase, (c+3) & 3, c+3, nc, Ah, Al, lda, Bw, ldb, mBase, nBase);
        else
            CP_COMMIT();                 // keep group count in lockstep

        uint32_t baseA = sbase + stg*STG_BYTES, baseB = baseA + ABYTES;
        #pragma unroll
        for (int ks = 0; ks < 2; ks++) {
            uint32_t afr[2][4], bfr[4][4];
            #pragma unroll
            for (int mi = 0; mi < 2; mi++) LDSM4(afr[mi], baseA + a_off[mi] + ks*32);
            #pragma unroll
            for (int p = 0; p < 4; p++)    LDSM4(bfr[p],  baseB + b_off[p]  + ks*32);
            #pragma unroll
            for (int mi = 0; mi < 2; mi++)
                #pragma unroll
                for (int ni = 0; ni < 8; ni++)
                    mma16816(acc[mi][ni], afr[mi], &bfr[ni >> 1][(ni & 1) * 2]);
        }
    }
    CP_WAIT0();

    if (sel == 0) {
        float* C = (float*)g_u;          // ldc = 1024
        #pragma unroll
        for (int mi = 0; mi < 2; mi++) {
            int r0 = mBase + warp_m*32 + mi*16 + (lane >> 2);
            #pragma unroll
            for (int ni = 0; ni < 8; ni++) {
                int col = nBase + warp_n*64 + ni*8 + (lane & 3)*2;
                *(float2*)(C + (size_t)r0*1024 + col)     = make_float2(acc[mi][ni][0], acc[mi][ni][1]);
                *(float2*)(C + (size_t)(r0+8)*1024 + col) = make_float2(acc[mi][ni][2], acc[mi][ni][3]);
            }
        }
    } else if (pair) {                   // y as (re,0) complex pairs
        #pragma unroll
        for (int mi = 0; mi < 2; mi++) {
            int r0 = mBase + warp_m*32 + mi*16 + (lane >> 2);
            #pragma unroll
            for (int ni = 0; ni < 8; ni++) {
                int col = nBase + warp_n*64 + ni*8 + (lane & 3)*2;
                *(float4*)(yout + 2*((size_t)r0*256 + col)) =
                    make_float4(acc[mi][ni][0], 0.f, acc[mi][ni][1], 0.f);
                *(float4*)(yout + 2*((size_t)(r0+8)*256 + col)) =
                    make_float4(acc[mi][ni][2], 0.f, acc[mi][ni][3], 0.f);
            }
        }
    } else {
        #pragma unroll
        for (int mi = 0; mi < 2; mi++) {
            int r0 = mBase + warp_m*32 + mi*16 + (lane >> 2);
            #pragma unroll
            for (int ni = 0; ni < 8; ni++) {
                int col = nBase + warp_n*64 + ni*8 + (lane & 3)*2;
                *(float2*)(yout + (size_t)r0*256 + col)     = make_float2(acc[mi][ni][0], acc[mi][ni][1]);
                *(float2*)(yout + (size_t)(r0+8)*256 + col) = make_float2(acc[mi][ni][2], acc[mi][ni][3]);
            }
        }
    }
}

// ---------------- chunked parallel scan (4 d's per thread, vectorized) -------
__global__ __launch_bounds__(256)
void scan_pass1_kernel() {
    int tid = blockIdx.x*blockDim.x + threadIdx.x;   // 65536 threads
    int dg = tid & 127;
    int ch = (tid >> 7) & (NCH-1);
    int b  = tid >> 13;
    if (b >= BATCH) return;
    int d = dg << 2;
    float2 A[4], x[4];
    #pragma unroll
    for (int q = 0; q < 4; q++) { A[q] = g_A[d+q]; x[q] = make_float2(0.f, 0.f); }
    const float4* up = (const float4*)(g_u + ((size_t)(b*LSEQ + ch*CHUNK))*DMODEL + d);
    #pragma unroll 4
    for (int s = 0; s < CHUNK; s++) {
        float4 u01 = up[0], u23 = up[1];
        float2 u[4] = { make_float2(u01.x,u01.y), make_float2(u01.z,u01.w),
                        make_float2(u23.x,u23.y), make_float2(u23.z,u23.w) };
        #pragma unroll
        for (int q = 0; q < 4; q++) {
            float nx = fmaf(A[q].x, x[q].x, fmaf(-A[q].y, x[q].y, u[q].x));
            float ny = fmaf(A[q].x, x[q].y, fmaf( A[q].y, x[q].x, u[q].y));
            x[q] = make_float2(nx, ny);
        }
        up += DMODEL/2;
    }
    float4* cr = (float4*)(g_carry + ((size_t)b*NCH + ch)*DMODEL + d);
    cr[0] = make_float4(x[0].x, x[0].y, x[1].x, x[1].y);
    cr[1] = make_float4(x[2].x, x[2].y, x[3].x, x[3].y);
}

__global__ __launch_bounds__(256)
void scan_pass2_kernel() {
    int tid = blockIdx.x*blockDim.x + threadIdx.x;
    if (tid >= BATCH*DMODEL) return;
    int d = tid & (DMODEL-1), b = tid >> 9;
    float2 Ac = g_Ac[d];
    float2 prev = make_float2(0.f, 0.f);
    for (int j = 0; j < NCH; j++) {
        size_t idx = ((size_t)b*NCH + j)*DMODEL + d;
        float2 cur = g_carry[idx];
        g_carry[idx] = prev;
        float nx = fmaf(Ac.x, prev.x, fmaf(-Ac.y, prev.y, cur.x));
        float ny = fmaf(Ac.x, prev.y, fmaf( Ac.y, prev.x, cur.y));
        prev = make_float2(nx, ny);
    }
}

__global__ __launch_bounds__(256)
void scan_pass3_kernel(float2* __restrict__ xext, int use_ext, float* __restrict__ xreal) {
    int tid = blockIdx.x*blockDim.x + threadIdx.x;   // 65536 threads
    int dg = tid & 127;
    int ch = (tid >> 7) & (NCH-1);
    int b  = tid >> 13;
    if (b >= BATCH) return;
    int d = dg << 2;
    float2 A[4], x[4];
    #pragma unroll
    for (int q = 0; q < 4; q++) A[q] = g_A[d+q];
    {
        const float4* cr = (const float4*)(g_carry + ((size_t)b*NCH + ch)*DMODEL + d);
        float4 c0 = cr[0], c1 = cr[1];
        x[0] = make_float2(c0.x,c0.y); x[1] = make_float2(c0.z,c0.w);
        x[2] = make_float2(c1.x,c1.y); x[3] = make_float2(c1.z,c1.w);
    }
    int m0 = b*LSEQ + ch*CHUNK;
    size_t base = (size_t)m0*DMODEL + d;
    const float4* up = (const float4*)(g_u + base);
    float4* xo = (float4*)((use_ext ? xext : g_x) + base);
    #pragma unroll 2
    for (int s = 0; s < CHUNK; s++) {
        float4 u01 = up[0], u23 = up[1];
        float2 u[4] = { make_float2(u01.x,u01.y), make_float2(u01.z,u01.w),
                        make_float2(u23.x,u23.y), make_float2(u23.z,u23.w) };
        #pragma unroll
        for (int q = 0; q < 4; q++) {
            float nx = fmaf(A[q].x, x[q].x, fmaf(-A[q].y, x[q].y, u[q].x));
            float ny = fmaf(A[q].x, x[q].y, fmaf( A[q].y, x[q].x, u[q].y));
            x[q] = make_float2(nx, ny);
        }
        xo[0] = make_float4(x[0].x, x[0].y, x[1].x, x[1].y);
        xo[1] = make_float4(x[2].x, x[2].y, x[3].x, x[3].y);
        if (xreal)
            *(float4*)(xreal + base + (size_t)s*DMODEL) =
                make_float4(x[0].x, x[1].x, x[2].x, x[3].x);
        size_t xrow = (size_t)(m0 + s)*K2;
        __half hr[4], lr[4], hi_[4], li_[4];
        #pragma unroll
        for (int q = 0; q < 4; q++) {
            split_f16(x[q].x, hr[q], lr[q]);
            split_f16(x[q].y, hi_[q], li_[q]);
        }
        *(uint2*)(g_X2h + xrow + d)       = *(uint2*)hr;
        *(uint2*)(g_X2l + xrow + d)       = *(uint2*)lr;
        *(uint2*)(g_X2h + xrow + 512 + d) = *(uint2*)hi_;
        *(uint2*)(g_X2l + xrow + 512 + d) = *(uint2*)li_;
        up += DMODEL/2;
        xo += DMODEL/2;
    }
}

// ---------------- host -------------------------------------------------------
extern "C" void kernel_launch(void* const* d_in, const int* in_sizes, int n_in,
                              void* d_out, int out_size) {
    const float* inputs    = (const float*)d_in[0];
    const float* nu_log    = (const float*)d_in[1];
    const float* theta_log = (const float*)d_in[2];
    const float* gamma_log = (const float*)d_in[3];
    const float* B_re      = (const float*)d_in[4];
    const float* B_im      = (const float*)d_in[5];
    const float* C_re      = (const float*)d_in[6];
    const float* C_im      = (const float*)d_in[7];
    const float* Dw        = (const float*)d_in[8];
    float* outF = (float*)d_out;

    const long long X = (long long)ML*DMODEL;
    const long long Y = (long long)ML*OUTDIM;
    float2* xext = 0; int use_ext = 0; float* xreal = 0;
    float* yout = 0; int pair = 0;
    long long os = (long long)out_size;
    if      (os == 2*X + Y)   { xext = (float2*)d_out; use_ext = 1; yout = outF + 2*X; }
    else if (os == 2*X + 2*Y) { xext = (float2*)d_out; use_ext = 1; yout = outF + 2*X; pair = 1; }
    else if (os == X + Y)     { xreal = outF; yout = outF + X; }
    else if (os == Y)         { yout = outF; }
    else if (os == 2*X)       { xext = (float2*)d_out; use_ext = 1; }
    else                      { xext = (float2*)d_out; use_ext = 1; yout = outF + 2*X; pair = 1; }

    cudaFuncSetAttribute(gemm_mma_kernel,
                         cudaFuncAttributeMaxDynamicSharedMemorySize, GEMM_SMEM);

    prep_A_kernel<<<2, 256>>>(nu_log, theta_log);
    prep_W1_kernel<<<(DMODEL*INDIM)/256, 256>>>(B_re, B_im, gamma_log);
    prep_W2_kernel<<<(OUTDIM*K2)/256, 256>>>(C_re, C_im, Dw);
    conv_inputs_kernel<<<(ML*32)/256, 256>>>(inputs);

    // G1: u = inputs x W1^T  (M=32768, N=1024, K=256 -> K'=512)
    gemm_mma_kernel<<<dim3(1024/128, ML/128), 256, GEMM_SMEM>>>(0, 0, 0);

    scan_pass1_kernel<<<(BATCH*NCH*DMODEL/4)/256, 256>>>();
    scan_pass2_kernel<<<(BATCH*DMODEL)/256, 256>>>();
    scan_pass3_kernel<<<(BATCH*NCH*DMODEL/4)/256, 256>>>(xext, use_ext, xreal);

    if (yout) {
        // G2: y = [xr|xi|inp] x [Cr|-Ci|D]^T  (M=32768, N=256, K=1280 -> K'=2560)
        gemm_mma_kernel<<<dim3(256/128, ML/128), 256, GEMM_SMEM>>>(1, yout, pair);
    }
}

// round 7
// speedup vs baseline: 4.2103x; 1.4766x over previous
#include <cuda_runtime.h>
#include <cuda_fp16.h>
#include <stdint.h>
#include <math.h>

#define BATCH   8
#define LSEQ    4096
#define INDIM   256
#define DMODEL  512
#define OUTDIM  256
#define ML      (BATCH*LSEQ)      /* 32768 */
#define CHUNK   64
#define NCH     (LSEQ/CHUNK)      /* 64 */
#define K2      1280              /* xr(512) + xi(512) + inp(256) */
#define BK      32
#define PAD     40                /* padded smem row, fp16 elems (80 B) */
#define STAGES  4
#define ABYTES  (128*PAD*2)       /* 10240 B per operand tile */
#define STG_BYTES (2*ABYTES)      /* 20480 B per stage */
#define GEMM_SMEM (STAGES*STG_BYTES) /* 81920 B */

// ---------------- device scratch -------------------------------------------
__device__ __align__(16) float2 g_u[(size_t)ML*DMODEL];      // 134 MB
__device__ __align__(16) float2 g_x[(size_t)ML*DMODEL];      // 134 MB fallback
__device__ __align__(16) float2 g_carry[(size_t)BATCH*NCH*DMODEL];
__device__ float2 g_A[DMODEL];
__device__ float2 g_Ac[DMODEL];
__device__ __align__(16) __half g_X2[(size_t)ML*K2];         // 80 MB (fp16 activations)
__device__ __align__(16) __half g_W1[1024*256];              // fp16 weights
__device__ __align__(16) __half g_W2[256*K2];

__device__ __forceinline__ float2 cmul(float2 a, float2 b) {
    return make_float2(a.x*b.x - a.y*b.y, a.x*b.y + a.y*b.x);
}

// ---------------- PTX helpers ------------------------------------------------
__device__ __forceinline__ uint32_t smem_u32(const void* p) {
    uint32_t a;
    asm("{ .reg .u64 t; cvta.to.shared.u64 t, %1; cvt.u32.u64 %0, t; }" : "=r"(a) : "l"(p));
    return a;
}
__device__ __forceinline__ void cp16(uint32_t dst, const void* src) {
    asm volatile("cp.async.cg.shared.global [%0], [%1], 16;" :: "r"(dst), "l"(src));
}
#define CP_COMMIT()  asm volatile("cp.async.commit_group;")
#define CP_WAIT2()   asm volatile("cp.async.wait_group 2;")
#define CP_WAIT0()   asm volatile("cp.async.wait_group 0;")

#define LDSM4(r, addr) \
    asm volatile("ldmatrix.sync.aligned.m8n8.x4.shared.b16 {%0,%1,%2,%3}, [%4];" \
        : "=r"((r)[0]),"=r"((r)[1]),"=r"((r)[2]),"=r"((r)[3]) : "r"(addr))

__device__ __forceinline__ void mma16816(float* c, const uint32_t* a, const uint32_t* b) {
    asm volatile("mma.sync.aligned.m16n8k16.row.col.f32.f16.f16.f32 "
        "{%0,%1,%2,%3}, {%4,%5,%6,%7}, {%8,%9}, {%0,%1,%2,%3};"
        : "+f"(c[0]), "+f"(c[1]), "+f"(c[2]), "+f"(c[3])
        : "r"(a[0]),"r"(a[1]),"r"(a[2]),"r"(a[3]), "r"(b[0]),"r"(b[1]));
}

// ---------------- prep ------------------------------------------------------
__global__ void prep_A_kernel(const float* __restrict__ nu_log,
                              const float* __restrict__ theta_log) {
    int d = blockIdx.x*blockDim.x + threadIdx.x;
    if (d >= DMODEL) return;
    float r  = expf(-expf(nu_log[d]));
    float th = expf(theta_log[d]);
    float2 A = make_float2(r*cosf(th), r*sinf(th));
    g_A[d] = A;
    float2 p = make_float2(1.f, 0.f);
    #pragma unroll 8
    for (int i = 0; i < CHUNK; i++) p = cmul(p, A);
    g_Ac[d] = p;
}

__global__ void prep_W1_kernel(const float* __restrict__ B_re,
                               const float* __restrict__ B_im,
                               const float* __restrict__ gamma_log) {
    int i = blockIdx.x*blockDim.x + threadIdx.x;       // d*256 + h
    if (i >= DMODEL*INDIM) return;
    int d = i >> 8, h = i & 255;
    float s = expf(gamma_log[d]);
    g_W1[(size_t)(2*d)*256   + h] = __float2half_rn(B_re[i]*s);
    g_W1[(size_t)(2*d+1)*256 + h] = __float2half_rn(B_im[i]*s);
}

__global__ void prep_W2_kernel(const float* __restrict__ C_re,
                               const float* __restrict__ C_im,
                               const float* __restrict__ Dw) {
    int i = blockIdx.x*blockDim.x + threadIdx.x;       // n*K2 + k
    if (i >= OUTDIM*K2) return;
    int n = i / K2, k = i % K2;
    float v;
    if      (k < 512)  v =  C_re[(size_t)n*512 + k];
    else if (k < 1024) v = -C_im[(size_t)n*512 + (k-512)];
    else               v =  Dw  [(size_t)n*256 + (k-1024)];
    g_W2[i] = __float2half_rn(v);
}

// vectorized: 8 floats in, 8 fp16 out (16B store)
__global__ void conv_inputs_kernel(const float* __restrict__ inp) {
    int i = blockIdx.x*blockDim.x + threadIdx.x;       // ML*32 groups
    int m = i >> 5, h8 = (i & 31) << 3;
    const float4* src = (const float4*)(inp + (size_t)m*INDIM + h8);
    float4 v0 = src[0], v1 = src[1];
    float vals[8] = {v0.x, v0.y, v0.z, v0.w, v1.x, v1.y, v1.z, v1.w};
    __half hv[8];
    #pragma unroll
    for (int j = 0; j < 8; j++) hv[j] = __float2half_rn(vals[j]);
    *(uint4*)(g_X2 + (size_t)m*K2 + 1024 + h8) = *(uint4*)hv;
}

// ---------------- mma.sync GEMM: C = A x B^T (fp16, single pass) ------------
// CTA 128(M) x 128(N), 8 warps (warp tile 32x64), BK=32, 4-stage cp.async ring.
__device__ __forceinline__ void issue_loads(
    int t, uint32_t sbase, int stg, int c,
    const __half* Aw, long lda,
    const __half* Bw, long ldb,
    int mBase, int nBase)
{
    long koff = (long)c * BK;
    uint32_t aBuf = sbase + stg*STG_BYTES;
    uint32_t bBuf = aBuf + ABYTES;
    #pragma unroll
    for (int r = 0; r < 2; r++) {               // 128 rows x 4 x 16B each operand
        int ci = t + r*256; int row = ci >> 2, j = ci & 3;
        cp16(aBuf + row*(PAD*2) + j*16, Aw + (size_t)(mBase+row)*lda + koff + j*8);
        cp16(bBuf + row*(PAD*2) + j*16, Bw + (size_t)(nBase+row)*ldb + koff + j*8);
    }
    CP_COMMIT();
}

__global__ __launch_bounds__(256, 2)
void gemm_mma_kernel(int sel, float* __restrict__ yout, int pair) {
    const __half *Aw, *Bw;
    long lda, ldb; int K;
    if (sel == 0) {   // G1: u = inputs x W1^T  (N total = 1024)
        Aw = g_X2 + 1024; lda = K2;
        Bw = g_W1; ldb = 256; K = 256;
    } else {          // G2: y = X2 x W2^T     (N total = 256)
        Aw = g_X2; lda = K2;
        Bw = g_W2; ldb = K2; K = K2;
    }
    const int NC = K / BK;
    const int t = threadIdx.x;
    const int wid = t >> 5, lane = t & 31;
    const int warp_m = wid & 3, warp_n = wid >> 2;
    const int mBase = blockIdx.y * 128;
    const int nBase = blockIdx.x * 128;

    extern __shared__ __align__(16) char smem[];
    uint32_t sbase = smem_u32(smem);

    float acc[2][8][4];
    #pragma unroll
    for (int mi = 0; mi < 2; mi++)
        #pragma unroll
        for (int ni = 0; ni < 8; ni++)
            #pragma unroll
            for (int q = 0; q < 4; q++) acc[mi][ni][q] = 0.f;

    uint32_t a_off[2], b_off[4];
    #pragma unroll
    for (int mi = 0; mi < 2; mi++) {
        int row = warp_m*32 + mi*16 + (lane & 15);
        int col = (lane >> 4) << 3;
        a_off[mi] = (uint32_t)((row*PAD + col) * 2);
    }
    #pragma unroll
    for (int p = 0; p < 4; p++) {
        int nrow = warp_n*64 + p*16 + (lane & 7) + ((lane >> 4) << 3);
        int col  = ((lane >> 3) & 1) << 3;
        b_off[p] = (uint32_t)((nrow*PAD + col) * 2);
    }

    // prologue: fill 3 of 4 stages
    issue_loads(t, sbase, 0, 0, Aw, lda, Bw, ldb, mBase, nBase);
    issue_loads(t, sbase, 1, 1, Aw, lda, Bw, ldb, mBase, nBase);
    issue_loads(t, sbase, 2, 2, Aw, lda, Bw, ldb, mBase, nBase);

    for (int c = 0; c < NC; c++) {
        int stg = c & 3;
        CP_WAIT2();                      // stage c ready (<=2 groups pending)
        __syncthreads();                 // all warps done with stage (c+3)&3
        if (c + 3 < NC)
            issue_loads(t, sbase, (c+3) & 3, c+3, Aw, lda, Bw, ldb, mBase, nBase);
        else
            CP_COMMIT();                 // keep group count in lockstep

        uint32_t baseA = sbase + stg*STG_BYTES, baseB = baseA + ABYTES;
        #pragma unroll
        for (int ks = 0; ks < 2; ks++) {
            uint32_t afr[2][4], bfr[4][4];
            #pragma unroll
            for (int mi = 0; mi < 2; mi++) LDSM4(afr[mi], baseA + a_off[mi] + ks*32);
            #pragma unroll
            for (int p = 0; p < 4; p++)    LDSM4(bfr[p],  baseB + b_off[p]  + ks*32);
            #pragma unroll
            for (int mi = 0; mi < 2; mi++)
                #pragma unroll
                for (int ni = 0; ni < 8; ni++)
                    mma16816(acc[mi][ni], afr[mi], &bfr[ni >> 1][(ni & 1) * 2]);
        }
    }
    CP_WAIT0();

    if (sel == 0) {
        float* C = (float*)g_u;          // ldc = 1024
        #pragma unroll
        for (int mi = 0; mi < 2; mi++) {
            int r0 = mBase + warp_m*32 + mi*16 + (lane >> 2);
            #pragma unroll
            for (int ni = 0; ni < 8; ni++) {
                int col = nBase + warp_n*64 + ni*8 + (lane & 3)*2;
                *(float2*)(C + (size_t)r0*1024 + col)     = make_float2(acc[mi][ni][0], acc[mi][ni][1]);
                *(float2*)(C + (size_t)(r0+8)*1024 + col) = make_float2(acc[mi][ni][2], acc[mi][ni][3]);
            }
        }
    } else if (pair) {                   // y as (re,0) complex pairs
        #pragma unroll
        for (int mi = 0; mi < 2; mi++) {
            int r0 = mBase + warp_m*32 + mi*16 + (lane >> 2);
            #pragma unroll
            for (int ni = 0; ni < 8; ni++) {
                int col = nBase + warp_n*64 + ni*8 + (lane & 3)*2;
                *(float4*)(yout + 2*((size_t)r0*256 + col)) =
                    make_float4(acc[mi][ni][0], 0.f, acc[mi][ni][1], 0.f);
                *(float4*)(yout + 2*((size_t)(r0+8)*256 + col)) =
                    make_float4(acc[mi][ni][2], 0.f, acc[mi][ni][3], 0.f);
            }
        }
    } else {
        #pragma unroll
        for (int mi = 0; mi < 2; mi++) {
            int r0 = mBase + warp_m*32 + mi*16 + (lane >> 2);
            #pragma unroll
            for (int ni = 0; ni < 8; ni++) {
                int col = nBase + warp_n*64 + ni*8 + (lane & 3)*2;
                *(float2*)(yout + (size_t)r0*256 + col)     = make_float2(acc[mi][ni][0], acc[mi][ni][1]);
                *(float2*)(yout + (size_t)(r0+8)*256 + col) = make_float2(acc[mi][ni][2], acc[mi][ni][3]);
            }
        }
    }
}

// ---------------- chunked parallel scan (4 d's per thread, vectorized) -------
__global__ __launch_bounds__(256)
void scan_pass1_kernel() {
    int tid = blockIdx.x*blockDim.x + threadIdx.x;   // 65536 threads
    int dg = tid & 127;
    int ch = (tid >> 7) & (NCH-1);
    int b  = tid >> 13;
    if (b >= BATCH) return;
    int d = dg << 2;
    float2 A[4], x[4];
    #pragma unroll
    for (int q = 0; q < 4; q++) { A[q] = g_A[d+q]; x[q] = make_float2(0.f, 0.f); }
    const float4* up = (const float4*)(g_u + ((size_t)(b*LSEQ + ch*CHUNK))*DMODEL + d);
    #pragma unroll 4
    for (int s = 0; s < CHUNK; s++) {
        float4 u01 = up[0], u23 = up[1];
        float2 u[4] = { make_float2(u01.x,u01.y), make_float2(u01.z,u01.w),
                        make_float2(u23.x,u23.y), make_float2(u23.z,u23.w) };
        #pragma unroll
        for (int q = 0; q < 4; q++) {
            float nx = fmaf(A[q].x, x[q].x, fmaf(-A[q].y, x[q].y, u[q].x));
            float ny = fmaf(A[q].x, x[q].y, fmaf( A[q].y, x[q].x, u[q].y));
            x[q] = make_float2(nx, ny);
        }
        up += DMODEL/2;
    }
    float4* cr = (float4*)(g_carry + ((size_t)b*NCH + ch)*DMODEL + d);
    cr[0] = make_float4(x[0].x, x[0].y, x[1].x, x[1].y);
    cr[1] = make_float4(x[2].x, x[2].y, x[3].x, x[3].y);
}

__global__ __launch_bounds__(256)
void scan_pass2_kernel() {
    int tid = blockIdx.x*blockDim.x + threadIdx.x;
    if (tid >= BATCH*DMODEL) return;
    int d = tid & (DMODEL-1), b = tid >> 9;
    float2 Ac = g_Ac[d];
    float2 prev = make_float2(0.f, 0.f);
    for (int j = 0; j < NCH; j++) {
        size_t idx = ((size_t)b*NCH + j)*DMODEL + d;
        float2 cur = g_carry[idx];
        g_carry[idx] = prev;
        float nx = fmaf(Ac.x, prev.x, fmaf(-Ac.y, prev.y, cur.x));
        float ny = fmaf(Ac.x, prev.y, fmaf( Ac.y, prev.x, cur.y));
        prev = make_float2(nx, ny);
    }
}

__global__ __launch_bounds__(256)
void scan_pass3_kernel(float2* __restrict__ xext, int use_ext, float* __restrict__ xreal) {
    int tid = blockIdx.x*blockDim.x + threadIdx.x;   // 65536 threads
    int dg = tid & 127;
    int ch = (tid >> 7) & (NCH-1);
    int b  = tid >> 13;
    if (b >= BATCH) return;
    int d = dg << 2;
    float2 A[4], x[4];
    #pragma unroll
    for (int q = 0; q < 4; q++) A[q] = g_A[d+q];
    {
        const float4* cr = (const float4*)(g_carry + ((size_t)b*NCH + ch)*DMODEL + d);
        float4 c0 = cr[0], c1 = cr[1];
        x[0] = make_float2(c0.x,c0.y); x[1] = make_float2(c0.z,c0.w);
        x[2] = make_float2(c1.x,c1.y); x[3] = make_float2(c1.z,c1.w);
    }
    int m0 = b*LSEQ + ch*CHUNK;
    size_t base = (size_t)m0*DMODEL + d;
    const float4* up = (const float4*)(g_u + base);
    float4* xo = (float4*)((use_ext ? xext : g_x) + base);
    #pragma unroll 2
    for (int s = 0; s < CHUNK; s++) {
        float4 u01 = up[0], u23 = up[1];
        float2 u[4] = { make_float2(u01.x,u01.y), make_float2(u01.z,u01.w),
                        make_float2(u23.x,u23.y), make_float2(u23.z,u23.w) };
        #pragma unroll
        for (int q = 0; q < 4; q++) {
            float nx = fmaf(A[q].x, x[q].x, fmaf(-A[q].y, x[q].y, u[q].x));
            float ny = fmaf(A[q].x, x[q].y, fmaf( A[q].y, x[q].x, u[q].y));
            x[q] = make_float2(nx, ny);
        }
        xo[0] = make_float4(x[0].x, x[0].y, x[1].x, x[1].y);
        xo[1] = make_float4(x[2].x, x[2].y, x[3].x, x[3].y);
        if (xreal)
            *(float4*)(xreal + base + (size_t)s*DMODEL) =
                make_float4(x[0].x, x[1].x, x[2].x, x[3].x);
        size_t xrow = (size_t)(m0 + s)*K2;
        __half hr[4], hi_[4];
        #pragma unroll
        for (int q = 0; q < 4; q++) {
            hr[q]  = __float2half_rn(x[q].x);
            hi_[q] = __float2half_rn(x[q].y);
        }
        *(uint2*)(g_X2 + xrow + d)       = *(uint2*)hr;
        *(uint2*)(g_X2 + xrow + 512 + d) = *(uint2*)hi_;
        up += DMODEL/2;
        xo += DMODEL/2;
    }
}

// ---------------- host -------------------------------------------------------
extern "C" void kernel_launch(void* const* d_in, const int* in_sizes, int n_in,
                              void* d_out, int out_size) {
    const float* inputs    = (const float*)d_in[0];
    const float* nu_log    = (const float*)d_in[1];
    const float* theta_log = (const float*)d_in[2];
    const float* gamma_log = (const float*)d_in[3];
    const float* B_re      = (const float*)d_in[4];
    const float* B_im      = (const float*)d_in[5];
    const float* C_re      = (const float*)d_in[6];
    const float* C_im      = (const float*)d_in[7];
    const float* Dw        = (const float*)d_in[8];
    float* outF = (float*)d_out;

    const long long X = (long long)ML*DMODEL;
    const long long Y = (long long)ML*OUTDIM;
    float2* xext = 0; int use_ext = 0; float* xreal = 0;
    float* yout = 0; int pair = 0;
    long long os = (long long)out_size;
    if      (os == 2*X + Y)   { xext = (float2*)d_out; use_ext = 1; yout = outF + 2*X; }
    else if (os == 2*X + 2*Y) { xext = (float2*)d_out; use_ext = 1; yout = outF + 2*X; pair = 1; }
    else if (os == X + Y)     { xreal = outF; yout = outF + X; }
    else if (os == Y)         { yout = outF; }
    else if (os == 2*X)       { xext = (float2*)d_out; use_ext = 1; }
    else                      { xext = (float2*)d_out; use_ext = 1; yout = outF + 2*X; pair = 1; }

    cudaFuncSetAttribute(gemm_mma_kernel,
                         cudaFuncAttributeMaxDynamicSharedMemorySize, GEMM_SMEM);

    prep_A_kernel<<<2, 256>>>(nu_log, theta_log);
    prep_W1_kernel<<<(DMODEL*INDIM)/256, 256>>>(B_re, B_im, gamma_log);
    prep_W2_kernel<<<(OUTDIM*K2)/256, 256>>>(C_re, C_im, Dw);
    conv_inputs_kernel<<<(ML*32)/256, 256>>>(inputs);

    // G1: u = inputs x W1^T  (M=32768, N=1024, K=256, single fp16 pass)
    gemm_mma_kernel<<<dim3(1024/128, ML/128), 256, GEMM_SMEM>>>(0, 0, 0);

    scan_pass1_kernel<<<(BATCH*NCH*DMODEL/4)/256, 256>>>();
    scan_pass2_kernel<<<(BATCH*DMODEL)/256, 256>>>();
    scan_pass3_kernel<<<(BATCH*NCH*DMODEL/4)/256, 256>>>(xext, use_ext, xreal);

    if (yout) {
        // G2: y = [xr|xi|inp] x [Cr|-Ci|D]^T  (M=32768, N=256, K=1280, single pass)
        gemm_mma_kernel<<<dim3(256/128, ML/128), 256, GEMM_SMEM>>>(1, yout, pair);
    }
}

// round 8
// speedup vs baseline: 4.5023x; 1.0693x over previous
#include <cuda_runtime.h>
#include <cuda_fp16.h>
#include <stdint.h>
#include <math.h>

#define BATCH   8
#define LSEQ    4096
#define INDIM   256
#define DMODEL  512
#define OUTDIM  256
#define ML      (BATCH*LSEQ)      /* 32768 */
#define CHUNK   64
#define NCH     (LSEQ/CHUNK)      /* 64 */
#define K2      1280              /* xr(512) + xi(512) + inp(256) */
#define BK      32
#define PAD     40                /* padded smem row, fp16 elems (80 B) */
#define STAGES  4
#define ABYTES  (128*PAD*2)       /* 10240 B per operand tile */
#define STG_BYTES (2*ABYTES)      /* 20480 B per stage */
#define GEMM_SMEM (STAGES*STG_BYTES) /* 81920 B */

// ---------------- device scratch -------------------------------------------
__device__ __align__(16) __half2 g_u[(size_t)ML*DMODEL];     // 64 MB (fp16 complex u)
__device__ __align__(16) float2 g_x[(size_t)ML*DMODEL];      // 134 MB fallback
__device__ __align__(16) float2 g_carry[(size_t)BATCH*NCH*DMODEL];
__device__ float2 g_A[DMODEL];
__device__ float2 g_Ac[DMODEL];
__device__ __align__(16) __half g_X2[(size_t)ML*K2];         // 80 MB (fp16 activations)
__device__ __align__(16) __half g_W1[1024*256];              // fp16 weights
__device__ __align__(16) __half g_W2[256*K2];

__device__ __forceinline__ float2 cmul(float2 a, float2 b) {
    return make_float2(a.x*b.x - a.y*b.y, a.x*b.y + a.y*b.x);
}

// ---------------- PTX helpers ------------------------------------------------
__device__ __forceinline__ uint32_t smem_u32(const void* p) {
    uint32_t a;
    asm("{ .reg .u64 t; cvta.to.shared.u64 t, %1; cvt.u32.u64 %0, t; }" : "=r"(a) : "l"(p));
    return a;
}
__device__ __forceinline__ void cp16(uint32_t dst, const void* src) {
    asm volatile("cp.async.cg.shared.global [%0], [%1], 16;" :: "r"(dst), "l"(src));
}
#define CP_COMMIT()  asm volatile("cp.async.commit_group;")
#define CP_WAIT2()   asm volatile("cp.async.wait_group 2;")
#define CP_WAIT0()   asm volatile("cp.async.wait_group 0;")

#define LDSM4(r, addr) \
    asm volatile("ldmatrix.sync.aligned.m8n8.x4.shared.b16 {%0,%1,%2,%3}, [%4];" \
        : "=r"((r)[0]),"=r"((r)[1]),"=r"((r)[2]),"=r"((r)[3]) : "r"(addr))

__device__ __forceinline__ void mma16816(float* c, const uint32_t* a, const uint32_t* b) {
    asm volatile("mma.sync.aligned.m16n8k16.row.col.f32.f16.f16.f32 "
        "{%0,%1,%2,%3}, {%4,%5,%6,%7}, {%8,%9}, {%0,%1,%2,%3};"
        : "+f"(c[0]), "+f"(c[1]), "+f"(c[2]), "+f"(c[3])
        : "r"(a[0]),"r"(a[1]),"r"(a[2]),"r"(a[3]), "r"(b[0]),"r"(b[1]));
}

// ---------------- prep ------------------------------------------------------
__global__ void prep_A_kernel(const float* __restrict__ nu_log,
                              const float* __restrict__ theta_log) {
    int d = blockIdx.x*blockDim.x + threadIdx.x;
    if (d >= DMODEL) return;
    float r  = expf(-expf(nu_log[d]));
    float th = expf(theta_log[d]);
    float2 A = make_float2(r*cosf(th), r*sinf(th));
    g_A[d] = A;
    float2 p = make_float2(1.f, 0.f);
    #pragma unroll 8
    for (int i = 0; i < CHUNK; i++) p = cmul(p, A);
    g_Ac[d] = p;
}

__global__ void prep_W1_kernel(const float* __restrict__ B_re,
                               const float* __restrict__ B_im,
                               const float* __restrict__ gamma_log) {
    int i = blockIdx.x*blockDim.x + threadIdx.x;       // d*256 + h
    if (i >= DMODEL*INDIM) return;
    int d = i >> 8, h = i & 255;
    float s = expf(gamma_log[d]);
    g_W1[(size_t)(2*d)*256   + h] = __float2half_rn(B_re[i]*s);
    g_W1[(size_t)(2*d+1)*256 + h] = __float2half_rn(B_im[i]*s);
}

__global__ void prep_W2_kernel(const float* __restrict__ C_re,
                               const float* __restrict__ C_im,
                               const float* __restrict__ Dw) {
    int i = blockIdx.x*blockDim.x + threadIdx.x;       // n*K2 + k
    if (i >= OUTDIM*K2) return;
    int n = i / K2, k = i % K2;
    float v;
    if      (k < 512)  v =  C_re[(size_t)n*512 + k];
    else if (k < 1024) v = -C_im[(size_t)n*512 + (k-512)];
    else               v =  Dw  [(size_t)n*256 + (k-1024)];
    g_W2[i] = __float2half_rn(v);
}

// vectorized: 8 floats in, 8 fp16 out (16B store)
__global__ void conv_inputs_kernel(const float* __restrict__ inp) {
    int i = blockIdx.x*blockDim.x + threadIdx.x;       // ML*32 groups
    int m = i >> 5, h8 = (i & 31) << 3;
    const float4* src = (const float4*)(inp + (size_t)m*INDIM + h8);
    float4 v0 = src[0], v1 = src[1];
    float vals[8] = {v0.x, v0.y, v0.z, v0.w, v1.x, v1.y, v1.z, v1.w};
    __half hv[8];
    #pragma unroll
    for (int j = 0; j < 8; j++) hv[j] = __float2half_rn(vals[j]);
    *(uint4*)(g_X2 + (size_t)m*K2 + 1024 + h8) = *(uint4*)hv;
}

// ---------------- mma.sync GEMM: C = A x B^T (fp16, single pass) ------------
// CTA 128(M) x 128(N), 8 warps (warp tile 32x64), BK=32, 4-stage cp.async ring.
__device__ __forceinline__ void issue_loads(
    int t, uint32_t sbase, int stg, int c,
    const __half* Aw, long lda,
    const __half* Bw, long ldb,
    int mBase, int nBase)
{
    long koff = (long)c * BK;
    uint32_t aBuf = sbase + stg*STG_BYTES;
    uint32_t bBuf = aBuf + ABYTES;
    #pragma unroll
    for (int r = 0; r < 2; r++) {               // 128 rows x 4 x 16B each operand
        int ci = t + r*256; int row = ci >> 2, j = ci & 3;
        cp16(aBuf + row*(PAD*2) + j*16, Aw + (size_t)(mBase+row)*lda + koff + j*8);
        cp16(bBuf + row*(PAD*2) + j*16, Bw + (size_t)(nBase+row)*ldb + koff + j*8);
    }
    CP_COMMIT();
}

__global__ __launch_bounds__(256, 2)
void gemm_mma_kernel(int sel, float* __restrict__ yout, int pair) {
    const __half *Aw, *Bw;
    long lda, ldb; int K;
    if (sel == 0) {   // G1: u = inputs x W1^T  (N total = 1024)
        Aw = g_X2 + 1024; lda = K2;
        Bw = g_W1; ldb = 256; K = 256;
    } else {          // G2: y = X2 x W2^T     (N total = 256)
        Aw = g_X2; lda = K2;
        Bw = g_W2; ldb = K2; K = K2;
    }
    const int NC = K / BK;
    const int t = threadIdx.x;
    const int wid = t >> 5, lane = t & 31;
    const int warp_m = wid & 3, warp_n = wid >> 2;
    const int mBase = blockIdx.y * 128;
    const int nBase = blockIdx.x * 128;

    extern __shared__ __align__(16) char smem[];
    uint32_t sbase = smem_u32(smem);

    float acc[2][8][4];
    #pragma unroll
    for (int mi = 0; mi < 2; mi++)
        #pragma unroll
        for (int ni = 0; ni < 8; ni++)
            #pragma unroll
            for (int q = 0; q < 4; q++) acc[mi][ni][q] = 0.f;

    uint32_t a_off[2], b_off[4];
    #pragma unroll
    for (int mi = 0; mi < 2; mi++) {
        int row = warp_m*32 + mi*16 + (lane & 15);
        int col = (lane >> 4) << 3;
        a_off[mi] = (uint32_t)((row*PAD + col) * 2);
    }
    #pragma unroll
    for (int p = 0; p < 4; p++) {
        int nrow = warp_n*64 + p*16 + (lane & 7) + ((lane >> 4) << 3);
        int col  = ((lane >> 3) & 1) << 3;
        b_off[p] = (uint32_t)((nrow*PAD + col) * 2);
    }

    // prologue: fill 3 of 4 stages
    issue_loads(t, sbase, 0, 0, Aw, lda, Bw, ldb, mBase, nBase);
    issue_loads(t, sbase, 1, 1, Aw, lda, Bw, ldb, mBase, nBase);
    issue_loads(t, sbase, 2, 2, Aw, lda, Bw, ldb, mBase, nBase);

    for (int c = 0; c < NC; c++) {
        int stg = c & 3;
        CP_WAIT2();                      // stage c ready (<=2 groups pending)
        __syncthreads();                 // all warps done with stage (c+3)&3
        if (c + 3 < NC)
            issue_loads(t, sbase, (c+3) & 3, c+3, Aw, lda, Bw, ldb, mBase, nBase);
        else
            CP_COMMIT();                 // keep group count in lockstep

        uint32_t baseA = sbase + stg*STG_BYTES, baseB = baseA + ABYTES;
        #pragma unroll
        for (int ks = 0; ks < 2; ks++) {
            uint32_t afr[2][4], bfr[4][4];
            #pragma unroll
            for (int mi = 0; mi < 2; mi++) LDSM4(afr[mi], baseA + a_off[mi] + ks*32);
            #pragma unroll
            for (int p = 0; p < 4; p++)    LDSM4(bfr[p],  baseB + b_off[p]  + ks*32);
            #pragma unroll
            for (int mi = 0; mi < 2; mi++)
                #pragma unroll
                for (int ni = 0; ni < 8; ni++)
                    mma16816(acc[mi][ni], afr[mi], &bfr[ni >> 1][(ni & 1) * 2]);
        }
    }
    CP_WAIT0();

    if (sel == 0) {                      // u epilogue: fp16 complex (half2 per element)
        #pragma unroll
        for (int mi = 0; mi < 2; mi++) {
            int r0 = mBase + warp_m*32 + mi*16 + (lane >> 2);
            #pragma unroll
            for (int ni = 0; ni < 8; ni++) {
                int col = nBase + warp_n*64 + ni*8 + (lane & 3)*2;   // even
                g_u[(size_t)r0*DMODEL + (col >> 1)] =
                    __floats2half2_rn(acc[mi][ni][0], acc[mi][ni][1]);
                g_u[(size_t)(r0+8)*DMODEL + (col >> 1)] =
                    __floats2half2_rn(acc[mi][ni][2], acc[mi][ni][3]);
            }
        }
    } else if (pair) {                   // y as (re,0) complex pairs
        #pragma unroll
        for (int mi = 0; mi < 2; mi++) {
            int r0 = mBase + warp_m*32 + mi*16 + (lane >> 2);
            #pragma unroll
            for (int ni = 0; ni < 8; ni++) {
                int col = nBase + warp_n*64 + ni*8 + (lane & 3)*2;
                *(float4*)(yout + 2*((size_t)r0*256 + col)) =
                    make_float4(acc[mi][ni][0], 0.f, acc[mi][ni][1], 0.f);
                *(float4*)(yout + 2*((size_t)(r0+8)*256 + col)) =
                    make_float4(acc[mi][ni][2], 0.f, acc[mi][ni][3], 0.f);
            }
        }
    } else {
        #pragma unroll
        for (int mi = 0; mi < 2; mi++) {
            int r0 = mBase + warp_m*32 + mi*16 + (lane >> 2);
            #pragma unroll
            for (int ni = 0; ni < 8; ni++) {
                int col = nBase + warp_n*64 + ni*8 + (lane & 3)*2;
                *(float2*)(yout + (size_t)r0*256 + col)     = make_float2(acc[mi][ni][0], acc[mi][ni][1]);
                *(float2*)(yout + (size_t)(r0+8)*256 + col) = make_float2(acc[mi][ni][2], acc[mi][ni][3]);
            }
        }
    }
}

// ---------------- chunked parallel scan (4 d's per thread, fp16 u) -----------
__global__ __launch_bounds__(256)
void scan_pass1_kernel() {
    int tid = blockIdx.x*blockDim.x + threadIdx.x;   // 65536 threads
    int dg = tid & 127;
    int ch = (tid >> 7) & (NCH-1);
    int b  = tid >> 13;
    if (b >= BATCH) return;
    int d = dg << 2;
    float2 A[4], x[4];
    #pragma unroll
    for (int q = 0; q < 4; q++) { A[q] = g_A[d+q]; x[q] = make_float2(0.f, 0.f); }
    const __half2* up = g_u + ((size_t)(b*LSEQ + ch*CHUNK))*DMODEL + d;
    #pragma unroll 4
    for (int s = 0; s < CHUNK; s++) {
        float4 raw = *(const float4*)up;             // 4 half2 complexes (16B)
        const __half2* hp = (const __half2*)&raw;
        #pragma unroll
        for (int q = 0; q < 4; q++) {
            float2 u = __half22float2(hp[q]);
            float nx = fmaf(A[q].x, x[q].x, fmaf(-A[q].y, x[q].y, u.x));
            float ny = fmaf(A[q].x, x[q].y, fmaf( A[q].y, x[q].x, u.y));
            x[q] = make_float2(nx, ny);
        }
        up += DMODEL;
    }
    float4* cr = (float4*)(g_carry + ((size_t)b*NCH + ch)*DMODEL + d);
    cr[0] = make_float4(x[0].x, x[0].y, x[1].x, x[1].y);
    cr[1] = make_float4(x[2].x, x[2].y, x[3].x, x[3].y);
}

__global__ __launch_bounds__(256)
void scan_pass2_kernel() {
    int tid = blockIdx.x*blockDim.x + threadIdx.x;
    if (tid >= BATCH*DMODEL) return;
    int d = tid & (DMODEL-1), b = tid >> 9;
    float2 Ac = g_Ac[d];
    float2 prev = make_float2(0.f, 0.f);
    for (int j = 0; j < NCH; j++) {
        size_t idx = ((size_t)b*NCH + j)*DMODEL + d;
        float2 cur = g_carry[idx];
        g_carry[idx] = prev;
        float nx = fmaf(Ac.x, prev.x, fmaf(-Ac.y, prev.y, cur.x));
        float ny = fmaf(Ac.x, prev.y, fmaf( Ac.y, prev.x, cur.y));
        prev = make_float2(nx, ny);
    }
}

__global__ __launch_bounds__(256)
void scan_pass3_kernel(float2* __restrict__ xext, int use_ext, float* __restrict__ xreal) {
    int tid = blockIdx.x*blockDim.x + threadIdx.x;   // 65536 threads
    int dg = tid & 127;
    int ch = (tid >> 7) & (NCH-1);
    int b  = tid >> 13;
    if (b >= BATCH) return;
    int d = dg << 2;
    float2 A[4], x[4];
    #pragma unroll
    for (int q = 0; q < 4; q++) A[q] = g_A[d+q];
    {
        const float4* cr = (const float4*)(g_carry + ((size_t)b*NCH + ch)*DMODEL + d);
        float4 c0 = cr[0], c1 = cr[1];
        x[0] = make_float2(c0.x,c0.y); x[1] = make_float2(c0.z,c0.w);
        x[2] = make_float2(c1.x,c1.y); x[3] = make_float2(c1.z,c1.w);
    }
    int m0 = b*LSEQ + ch*CHUNK;
    size_t base = (size_t)m0*DMODEL + d;
    const __half2* up = g_u + base;
    float4* xo = (float4*)((use_ext ? xext : g_x) + base);
    #pragma unroll 2
    for (int s = 0; s < CHUNK; s++) {
        float4 raw = *(const float4*)up;
        const __half2* hp = (const __half2*)&raw;
        #pragma unroll
        for (int q = 0; q < 4; q++) {
            float2 u = __half22float2(hp[q]);
            float nx = fmaf(A[q].x, x[q].x, fmaf(-A[q].y, x[q].y, u.x));
            float ny = fmaf(A[q].x, x[q].y, fmaf( A[q].y, x[q].x, u.y));
            x[q] = make_float2(nx, ny);
        }
        xo[0] = make_float4(x[0].x, x[0].y, x[1].x, x[1].y);
        xo[1] = make_float4(x[2].x, x[2].y, x[3].x, x[3].y);
        if (xreal)
            *(float4*)(xreal + base + (size_t)s*DMODEL) =
                make_float4(x[0].x, x[1].x, x[2].x, x[3].x);
        size_t xrow = (size_t)(m0 + s)*K2;
        __half hr[4], hi_[4];
        #pragma unroll
        for (int q = 0; q < 4; q++) {
            hr[q]  = __float2half_rn(x[q].x);
            hi_[q] = __float2half_rn(x[q].y);
        }
        *(uint2*)(g_X2 + xrow + d)       = *(uint2*)hr;
        *(uint2*)(g_X2 + xrow + 512 + d) = *(uint2*)hi_;
        up += DMODEL;
        xo += DMODEL/2;
    }
}

// ---------------- host -------------------------------------------------------
extern "C" void kernel_launch(void* const* d_in, const int* in_sizes, int n_in,
                              void* d_out, int out_size) {
    const float* inputs    = (const float*)d_in[0];
    const float* nu_log    = (const float*)d_in[1];
    const float* theta_log = (const float*)d_in[2];
    const float* gamma_log = (const float*)d_in[3];
    const float* B_re      = (const float*)d_in[4];
    const float* B_im      = (const float*)d_in[5];
    const float* C_re      = (const float*)d_in[6];
    const float* C_im      = (const float*)d_in[7];
    const float* Dw        = (const float*)d_in[8];
    float* outF = (float*)d_out;

    const long long X = (long long)ML*DMODEL;
    const long long Y = (long long)ML*OUTDIM;
    float2* xext = 0; int use_ext = 0; float* xreal = 0;
    float* yout = 0; int pair = 0;
    long long os = (long long)out_size;
    if      (os == 2*X + Y)   { xext = (float2*)d_out; use_ext = 1; yout = outF + 2*X; }
    else if (os == 2*X + 2*Y) { xext = (float2*)d_out; use_ext = 1; yout = outF + 2*X; pair = 1; }
    else if (os == X + Y)     { xreal = outF; yout = outF + X; }
    else if (os == Y)         { yout = outF; }
    else if (os == 2*X)       { xext = (float2*)d_out; use_ext = 1; }
    else                      { xext = (float2*)d_out; use_ext = 1; yout = outF + 2*X; pair = 1; }

    cudaFuncSetAttribute(gemm_mma_kernel,
                         cudaFuncAttributeMaxDynamicSharedMemorySize, GEMM_SMEM);

    prep_A_kernel<<<2, 256>>>(nu_log, theta_log);
    prep_W1_kernel<<<(DMODEL*INDIM)/256, 256>>>(B_re, B_im, gamma_log);
    prep_W2_kernel<<<(OUTDIM*K2)/256, 256>>>(C_re, C_im, Dw);
    conv_inputs_kernel<<<(ML*32)/256, 256>>>(inputs);

    // G1: u = inputs x W1^T  (M=32768, N=1024, K=256, single fp16 pass)
    gemm_mma_kernel<<<dim3(1024/128, ML/128), 256, GEMM_SMEM>>>(0, 0, 0);

    scan_pass1_kernel<<<(BATCH*NCH*DMODEL/4)/256, 256>>>();
    scan_pass2_kernel<<<(BATCH*DMODEL)/256, 256>>>();
    scan_pass3_kernel<<<(BATCH*NCH*DMODEL/4)/256, 256>>>(xext, use_ext, xreal);

    if (yout) {
        // G2: y = [xr|xi|inp] x [Cr|-Ci|D]^T  (M=32768, N=256, K=1280, single pass)
        gemm_mma_kernel<<<dim3(256/128, ML/128), 256, GEMM_SMEM>>>(1, yout, pair);
    }
}

// round 9
// speedup vs baseline: 4.5045x; 1.0005x over previous
#include <cuda_runtime.h>
#include <cuda_fp16.h>
#include <stdint.h>
#include <math.h>

#define BATCH   8
#define LSEQ    4096
#define INDIM   256
#define DMODEL  512
#define OUTDIM  256
#define ML      (BATCH*LSEQ)      /* 32768 */
#define CHUNK   64
#define NCH     (LSEQ/CHUNK)      /* 64 */
#define K2      1280              /* xr(512) + xi(512) + inp(256) */
#define BK      32
#define PAD     40                /* padded smem row, fp16 elems (80 B) */
#define STAGES  4
#define ABYTES  (128*PAD*2)       /* 10240 B per operand tile (128-row) */
#define STG_BYTES (2*ABYTES)
#define GEMM_SMEM (STAGES*STG_BYTES)    /* 81920 B */
#define ABYTES64 (64*PAD*2)       /* 5120 B per operand tile (64-row) */
#define STG64    (2*ABYTES64)
#define GEMM64_SMEM (STAGES*STG64)      /* 40960 B */

// ---------------- device scratch -------------------------------------------
__device__ __align__(16) __half2 g_u[(size_t)ML*DMODEL];     // 64 MB (fp16 complex u)
__device__ __align__(16) float2 g_x[(size_t)ML*DMODEL];      // fallback
__device__ __align__(16) float2 g_carry[(size_t)BATCH*NCH*DMODEL];
__device__ float2 g_A[DMODEL];
__device__ float2 g_Ac[DMODEL];
__device__ __align__(16) __half g_X2[(size_t)ML*K2];         // 80 MB (fp16 activations)
__device__ __align__(16) __half g_W1[1024*256];              // fp16 weights
__device__ __align__(16) __half g_W2[256*K2];

__device__ __forceinline__ float2 cmul(float2 a, float2 b) {
    return make_float2(a.x*b.x - a.y*b.y, a.x*b.y + a.y*b.x);
}

// ---------------- PTX helpers ------------------------------------------------
__device__ __forceinline__ uint32_t smem_u32(const void* p) {
    uint32_t a;
    asm("{ .reg .u64 t; cvta.to.shared.u64 t, %1; cvt.u32.u64 %0, t; }" : "=r"(a) : "l"(p));
    return a;
}
__device__ __forceinline__ void cp16(uint32_t dst, const void* src) {
    asm volatile("cp.async.cg.shared.global [%0], [%1], 16;" :: "r"(dst), "l"(src));
}
#define CP_COMMIT()  asm volatile("cp.async.commit_group;")
#define CP_WAIT2()   asm volatile("cp.async.wait_group 2;")
#define CP_WAIT0()   asm volatile("cp.async.wait_group 0;")

#define LDSM4(r, addr) \
    asm volatile("ldmatrix.sync.aligned.m8n8.x4.shared.b16 {%0,%1,%2,%3}, [%4];" \
        : "=r"((r)[0]),"=r"((r)[1]),"=r"((r)[2]),"=r"((r)[3]) : "r"(addr))

__device__ __forceinline__ void mma16816(float* c, const uint32_t* a, const uint32_t* b) {
    asm volatile("mma.sync.aligned.m16n8k16.row.col.f32.f16.f16.f32 "
        "{%0,%1,%2,%3}, {%4,%5,%6,%7}, {%8,%9}, {%0,%1,%2,%3};"
        : "+f"(c[0]), "+f"(c[1]), "+f"(c[2]), "+f"(c[3])
        : "r"(a[0]),"r"(a[1]),"r"(a[2]),"r"(a[3]), "r"(b[0]),"r"(b[1]));
}

// ---------------- fused prep: conv(4096) | W1(512) | W2(1280) | A(2) ---------
__global__ void prep_all_kernel(const float* __restrict__ inp,
                                const float* __restrict__ nu_log,
                                const float* __restrict__ theta_log,
                                const float* __restrict__ gamma_log,
                                const float* __restrict__ B_re,
                                const float* __restrict__ B_im,
                                const float* __restrict__ C_re,
                                const float* __restrict__ C_im,
                                const float* __restrict__ Dw) {
    int bid = blockIdx.x;
    int t = threadIdx.x;
    if (bid < 4096) {                                   // conv inputs -> X2 fp16
        int i = bid*256 + t;
        int m = i >> 5, h8 = (i & 31) << 3;
        const float4* src = (const float4*)(inp + (size_t)m*INDIM + h8);
        float4 v0 = src[0], v1 = src[1];
        float vals[8] = {v0.x, v0.y, v0.z, v0.w, v1.x, v1.y, v1.z, v1.w};
        __half hv[8];
        #pragma unroll
        for (int j = 0; j < 8; j++) hv[j] = __float2half_rn(vals[j]);
        *(uint4*)(g_X2 + (size_t)m*K2 + 1024 + h8) = *(uint4*)hv;
    } else if (bid < 4096 + 512) {                      // W1
        int i = (bid - 4096)*256 + t;                   // d*256 + h
        int d = i >> 8, h = i & 255;
        float s = expf(gamma_log[d]);
        g_W1[(size_t)(2*d)*256   + h] = __float2half_rn(B_re[i]*s);
        g_W1[(size_t)(2*d+1)*256 + h] = __float2half_rn(B_im[i]*s);
    } else if (bid < 4096 + 512 + 1280) {               // W2
        int i = (bid - 4608)*256 + t;                   // n*K2 + k
        int n = i / K2, k = i % K2;
        float v;
        if      (k < 512)  v =  C_re[(size_t)n*512 + k];
        else if (k < 1024) v = -C_im[(size_t)n*512 + (k-512)];
        else               v =  Dw  [(size_t)n*256 + (k-1024)];
        g_W2[i] = __float2half_rn(v);
    } else {                                            // A
        int d = (bid - 5888)*256 + t;
        if (d >= DMODEL) return;
        float r  = expf(-expf(nu_log[d]));
        float th = expf(theta_log[d]);
        float2 A = make_float2(r*cosf(th), r*sinf(th));
        g_A[d] = A;
        float2 p = make_float2(1.f, 0.f);
        #pragma unroll 8
        for (int i2 = 0; i2 < CHUNK; i2++) p = cmul(p, A);
        g_Ac[d] = p;
    }
}

// ---------------- G1: 128x128 tiles, u = inputs x W1^T ----------------------
__device__ __forceinline__ void issue_loads128(
    int t, uint32_t sbase, int stg, int c,
    const __half* Aw, long lda,
    const __half* Bw, long ldb,
    int mBase, int nBase)
{
    long koff = (long)c * BK;
    uint32_t aBuf = sbase + stg*STG_BYTES;
    uint32_t bBuf = aBuf + ABYTES;
    #pragma unroll
    for (int r = 0; r < 2; r++) {
        int ci = t + r*256; int row = ci >> 2, j = ci & 3;
        cp16(aBuf + row*(PAD*2) + j*16, Aw + (size_t)(mBase+row)*lda + koff + j*8);
        cp16(bBuf + row*(PAD*2) + j*16, Bw + (size_t)(nBase+row)*ldb + koff + j*8);
    }
    CP_COMMIT();
}

__global__ __launch_bounds__(256, 2)
void gemm_g1_kernel() {
    const __half* Aw = g_X2 + 1024;  const long lda = K2;
    const __half* Bw = g_W1;         const long ldb = 256;
    const int NC = 256 / BK;         // 8
    const int t = threadIdx.x;
    const int wid = t >> 5, lane = t & 31;
    const int warp_m = wid & 3, warp_n = wid >> 2;
    const int mBase = blockIdx.y * 128;
    const int nBase = blockIdx.x * 128;

    extern __shared__ __align__(16) char smem[];
    uint32_t sbase = smem_u32(smem);

    float acc[2][8][4];
    #pragma unroll
    for (int mi = 0; mi < 2; mi++)
        #pragma unroll
        for (int ni = 0; ni < 8; ni++)
            #pragma unroll
            for (int q = 0; q < 4; q++) acc[mi][ni][q] = 0.f;

    uint32_t a_off[2], b_off[4];
    #pragma unroll
    for (int mi = 0; mi < 2; mi++) {
        int row = warp_m*32 + mi*16 + (lane & 15);
        int col = (lane >> 4) << 3;
        a_off[mi] = (uint32_t)((row*PAD + col) * 2);
    }
    #pragma unroll
    for (int p = 0; p < 4; p++) {
        int nrow = warp_n*64 + p*16 + (lane & 7) + ((lane >> 4) << 3);
        int col  = ((lane >> 3) & 1) << 3;
        b_off[p] = (uint32_t)((nrow*PAD + col) * 2);
    }

    issue_loads128(t, sbase, 0, 0, Aw, lda, Bw, ldb, mBase, nBase);
    issue_loads128(t, sbase, 1, 1, Aw, lda, Bw, ldb, mBase, nBase);
    issue_loads128(t, sbase, 2, 2, Aw, lda, Bw, ldb, mBase, nBase);

    for (int c = 0; c < NC; c++) {
        int stg = c & 3;
        CP_WAIT2();
        __syncthreads();
        if (c + 3 < NC)
            issue_loads128(t, sbase, (c+3) & 3, c+3, Aw, lda, Bw, ldb, mBase, nBase);
        else
            CP_COMMIT();

        uint32_t baseA = sbase + stg*STG_BYTES, baseB = baseA + ABYTES;
        #pragma unroll
        for (int ks = 0; ks < 2; ks++) {
            uint32_t afr[2][4], bfr[4][4];
            #pragma unroll
            for (int mi = 0; mi < 2; mi++) LDSM4(afr[mi], baseA + a_off[mi] + ks*32);
            #pragma unroll
            for (int p = 0; p < 4; p++)    LDSM4(bfr[p],  baseB + b_off[p]  + ks*32);
            #pragma unroll
            for (int mi = 0; mi < 2; mi++)
                #pragma unroll
                for (int ni = 0; ni < 8; ni++)
                    mma16816(acc[mi][ni], afr[mi], &bfr[ni >> 1][(ni & 1) * 2]);
        }
    }
    CP_WAIT0();

    // u epilogue: fp16 complex (half2 per element)
    #pragma unroll
    for (int mi = 0; mi < 2; mi++) {
        int r0 = mBase + warp_m*32 + mi*16 + (lane >> 2);
        #pragma unroll
        for (int ni = 0; ni < 8; ni++) {
            int col = nBase + warp_n*64 + ni*8 + (lane & 3)*2;   // even
            g_u[(size_t)r0*DMODEL + (col >> 1)] =
                __floats2half2_rn(acc[mi][ni][0], acc[mi][ni][1]);
            g_u[(size_t)(r0+8)*DMODEL + (col >> 1)] =
                __floats2half2_rn(acc[mi][ni][2], acc[mi][ni][3]);
        }
    }
}

// ---------------- G2: 64x64 tiles, y = X2 x W2^T (beats wave quantization) --
__device__ __forceinline__ void issue_loads64(
    int t, uint32_t sbase, int stg, int c,
    int mBase, int nBase)
{
    long koff = (long)c * BK;
    uint32_t aBuf = sbase + stg*STG64;
    uint32_t bBuf = aBuf + ABYTES64;
    int row = t >> 2, j = t & 3;        // 64 rows x 4 x 16B, 256 ops per operand
    cp16(aBuf + row*(PAD*2) + j*16, g_X2 + (size_t)(mBase+row)*K2 + koff + j*8);
    cp16(bBuf + row*(PAD*2) + j*16, g_W2 + (size_t)(nBase+row)*K2 + koff + j*8);
    CP_COMMIT();
}

__global__ __launch_bounds__(256, 2)
void gemm_g2_kernel(float* __restrict__ yout, int pair) {
    const int NC = K2 / BK;          // 40
    const int t = threadIdx.x;
    const int wid = t >> 5, lane = t & 31;
    const int warp_m = wid & 3, warp_n = wid >> 2;   // 4 x 2, warp tile 16x32
    const int mBase = blockIdx.y * 64;
    const int nBase = blockIdx.x * 64;

    extern __shared__ __align__(16) char smem[];
    uint32_t sbase = smem_u32(smem);

    float acc[4][4];
    #pragma unroll
    for (int ni = 0; ni < 4; ni++)
        #pragma unroll
        for (int q = 0; q < 4; q++) acc[ni][q] = 0.f;

    uint32_t a_off, b_off[2];
    {
        int row = warp_m*16 + (lane & 15);
        int col = (lane >> 4) << 3;
        a_off = (uint32_t)((row*PAD + col) * 2);
    }
    #pragma unroll
    for (int p = 0; p < 2; p++) {
        int nrow = warp_n*32 + p*16 + (lane & 7) + ((lane >> 4) << 3);
        int col  = ((lane >> 3) & 1) << 3;
        b_off[p] = (uint32_t)((nrow*PAD + col) * 2);
    }

    issue_loads64(t, sbase, 0, 0, mBase, nBase);
    issue_loads64(t, sbase, 1, 1, mBase, nBase);
    issue_loads64(t, sbase, 2, 2, mBase, nBase);

    for (int c = 0; c < NC; c++) {
        int stg = c & 3;
        CP_WAIT2();
        __syncthreads();
        if (c + 3 < NC)
            issue_loads64(t, sbase, (c+3) & 3, c+3, mBase, nBase);
        else
            CP_COMMIT();

        uint32_t baseA = sbase + stg*STG64, baseB = baseA + ABYTES64;
        #pragma unroll
        for (int ks = 0; ks < 2; ks++) {
            uint32_t afr[4], bfr[2][4];
            LDSM4(afr, baseA + a_off + ks*32);
            #pragma unroll
            for (int p = 0; p < 2; p++) LDSM4(bfr[p], baseB + b_off[p] + ks*32);
            #pragma unroll
            for (int ni = 0; ni < 4; ni++)
                mma16816(acc[ni], afr, &bfr[ni >> 1][(ni & 1) * 2]);
        }
    }
    CP_WAIT0();

    int r0 = mBase + warp_m*16 + (lane >> 2);
    if (pair) {
        #pragma unroll
        for (int ni = 0; ni < 4; ni++) {
            int col = nBase + warp_n*32 + ni*8 + (lane & 3)*2;
            *(float4*)(yout + 2*((size_t)r0*256 + col)) =
                make_float4(acc[ni][0], 0.f, acc[ni][1], 0.f);
            *(float4*)(yout + 2*((size_t)(r0+8)*256 + col)) =
                make_float4(acc[ni][2], 0.f, acc[ni][3], 0.f);
        }
    } else {
        #pragma unroll
        for (int ni = 0; ni < 4; ni++) {
            int col = nBase + warp_n*32 + ni*8 + (lane & 3)*2;
            *(float2*)(yout + (size_t)r0*256 + col)     = make_float2(acc[ni][0], acc[ni][1]);
            *(float2*)(yout + (size_t)(r0+8)*256 + col) = make_float2(acc[ni][2], acc[ni][3]);
        }
    }
}

// ---------------- chunked parallel scan (4 d's per thread, fp16 u) -----------
__global__ __launch_bounds__(256)
void scan_pass1_kernel() {
    int tid = blockIdx.x*blockDim.x + threadIdx.x;   // 65536 threads
    int dg = tid & 127;
    int ch = (tid >> 7) & (NCH-1);
    int b  = tid >> 13;
    if (b >= BATCH) return;
    int d = dg << 2;
    float2 A[4], x[4];
    #pragma unroll
    for (int q = 0; q < 4; q++) { A[q] = g_A[d+q]; x[q] = make_float2(0.f, 0.f); }
    const __half2* up = g_u + ((size_t)(b*LSEQ + ch*CHUNK))*DMODEL + d;
    #pragma unroll 4
    for (int s = 0; s < CHUNK; s++) {
        float4 raw = *(const float4*)up;             // 4 half2 complexes (16B)
        const __half2* hp = (const __half2*)&raw;
        #pragma unroll
        for (int q = 0; q < 4; q++) {
            float2 u = __half22float2(hp[q]);
            float nx = fmaf(A[q].x, x[q].x, fmaf(-A[q].y, x[q].y, u.x));
            float ny = fmaf(A[q].x, x[q].y, fmaf( A[q].y, x[q].x, u.y));
            x[q] = make_float2(nx, ny);
        }
        up += DMODEL;
    }
    float4* cr = (float4*)(g_carry + ((size_t)b*NCH + ch)*DMODEL + d);
    cr[0] = make_float4(x[0].x, x[0].y, x[1].x, x[1].y);
    cr[1] = make_float4(x[2].x, x[2].y, x[3].x, x[3].y);
}

__global__ __launch_bounds__(256)
void scan_pass2_kernel() {
    int tid = blockIdx.x*blockDim.x + threadIdx.x;
    if (tid >= BATCH*DMODEL) return;
    int d = tid & (DMODEL-1), b = tid >> 9;
    float2 Ac = g_Ac[d];
    float2 prev = make_float2(0.f, 0.f);
    for (int j = 0; j < NCH; j++) {
        size_t idx = ((size_t)b*NCH + j)*DMODEL + d;
        float2 cur = g_carry[idx];
        g_carry[idx] = prev;
        float nx = fmaf(Ac.x, prev.x, fmaf(-Ac.y, prev.y, cur.x));
        float ny = fmaf(Ac.x, prev.y, fmaf( Ac.y, prev.x, cur.y));
        prev = make_float2(nx, ny);
    }
}

__global__ __launch_bounds__(256)
void scan_pass3_kernel(float2* __restrict__ xext, int use_ext, float* __restrict__ xreal) {
    int tid = blockIdx.x*blockDim.x + threadIdx.x;   // 65536 threads
    int dg = tid & 127;
    int ch = (tid >> 7) & (NCH-1);
    int b  = tid >> 13;
    if (b >= BATCH) return;
    int d = dg << 2;
    float2 A[4], x[4];
    #pragma unroll
    for (int q = 0; q < 4; q++) A[q] = g_A[d+q];
    {
        const float4* cr = (const float4*)(g_carry + ((size_t)b*NCH + ch)*DMODEL + d);
        float4 c0 = cr[0], c1 = cr[1];
        x[0] = make_float2(c0.x,c0.y); x[1] = make_float2(c0.z,c0.w);
        x[2] = make_float2(c1.x,c1.y); x[3] = make_float2(c1.z,c1.w);
    }
    int m0 = b*LSEQ + ch*CHUNK;
    size_t base = (size_t)m0*DMODEL + d;
    const __half2* up = g_u + base;
    float4* xo = (float4*)((use_ext ? xext : g_x) + base);
    #pragma unroll 2
    for (int s = 0; s < CHUNK; s++) {
        float4 raw = *(const float4*)up;
        const __half2* hp = (const __half2*)&raw;
        #pragma unroll
        for (int q = 0; q < 4; q++) {
            float2 u = __half22float2(hp[q]);
            float nx = fmaf(A[q].x, x[q].x, fmaf(-A[q].y, x[q].y, u.x));
            float ny = fmaf(A[q].x, x[q].y, fmaf( A[q].y, x[q].x, u.y));
            x[q] = make_float2(nx, ny);
        }
        xo[0] = make_float4(x[0].x, x[0].y, x[1].x, x[1].y);
        xo[1] = make_float4(x[2].x, x[2].y, x[3].x, x[3].y);
        if (xreal)
            *(float4*)(xreal + base + (size_t)s*DMODEL) =
                make_float4(x[0].x, x[1].x, x[2].x, x[3].x);
        size_t xrow = (size_t)(m0 + s)*K2;
        __half hr[4], hi_[4];
        #pragma unroll
        for (int q = 0; q < 4; q++) {
            hr[q]  = __float2half_rn(x[q].x);
            hi_[q] = __float2half_rn(x[q].y);
        }
        *(uint2*)(g_X2 + xrow + d)       = *(uint2*)hr;
        *(uint2*)(g_X2 + xrow + 512 + d) = *(uint2*)hi_;
        up += DMODEL;
        xo += DMODEL/2;
    }
}

// ---------------- host -------------------------------------------------------
extern "C" void kernel_launch(void* const* d_in, const int* in_sizes, int n_in,
                              void* d_out, int out_size) {
    const float* inputs    = (const float*)d_in[0];
    const float* nu_log    = (const float*)d_in[1];
    const float* theta_log = (const float*)d_in[2];
    const float* gamma_log = (const float*)d_in[3];
    const float* B_re      = (const float*)d_in[4];
    const float* B_im      = (const float*)d_in[5];
    const float* C_re      = (const float*)d_in[6];
    const float* C_im      = (const float*)d_in[7];
    const float* Dw        = (const float*)d_in[8];
    float* outF = (float*)d_out;

    const long long X = (long long)ML*DMODEL;
    const long long Y = (long long)ML*OUTDIM;
    float2* xext = 0; int use_ext = 0; float* xreal = 0;
    float* yout = 0; int pair = 0;
    long long os = (long long)out_size;
    if      (os == 2*X + Y)   { xext = (float2*)d_out; use_ext = 1; yout = outF + 2*X; }
    else if (os == 2*X + 2*Y) { xext = (float2*)d_out; use_ext = 1; yout = outF + 2*X; pair = 1; }
    else if (os == X + Y)     { xreal = outF; yout = outF + X; }
    else if (os == Y)         { yout = outF; }
    else if (os == 2*X)       { xext = (float2*)d_out; use_ext = 1; }
    else                      { xext = (float2*)d_out; use_ext = 1; yout = outF + 2*X; pair = 1; }

    cudaFuncSetAttribute(gemm_g1_kernel,
                         cudaFuncAttributeMaxDynamicSharedMemorySize, GEMM_SMEM);
    cudaFuncSetAttribute(gemm_g2_kernel,
                         cudaFuncAttributeMaxDynamicSharedMemorySize, GEMM64_SMEM);

    // fused preps: conv(4096) | W1(512) | W2(1280) | A(2)
    prep_all_kernel<<<5890, 256>>>(inputs, nu_log, theta_log, gamma_log,
                                   B_re, B_im, C_re, C_im, Dw);

    // G1: u = inputs x W1^T  (M=32768, N=1024, K=256)
    gemm_g1_kernel<<<dim3(1024/128, ML/128), 256, GEMM_SMEM>>>();

    scan_pass1_kernel<<<(BATCH*NCH*DMODEL/4)/256, 256>>>();
    scan_pass2_kernel<<<(BATCH*DMODEL)/256, 256>>>();
    scan_pass3_kernel<<<(BATCH*NCH*DMODEL/4)/256, 256>>>(xext, use_ext, xreal);

    if (yout) {
        // G2: y = [xr|xi|inp] x [Cr|-Ci|D]^T  (M=32768, N=256, K=1280), 64x64 tiles
        gemm_g2_kernel<<<dim3(256/64, ML/64), 256, GEMM64_SMEM>>>(yout, pair);
    }
}